// round 14
// baseline (speedup 1.0000x reference)
#include <cuda_runtime.h>
#include <cuda_bf16.h>
#include <math.h>
#include <stdint.h>

#define B_  4
#define T_  2305
#define C_  384
#define H_  6
#define BH_ (B_*H_)          // 24
#define DH  64
#define HW  48
#define M_  (B_*T_)          // 9220 rows
#define BN_EPS 1e-5f
#define NKT 37               // key tiles of 64
#define KT  (NKT*64)         // 2368 padded keys
#define QPAD 2432            // 19*128 padded queries
#define NP  192              // k-pairs per row (C/2)

// Attention interleaved fragment layout (global K/V), unchanged since R8.
__device__ __forceinline__ int pslot(int p)
{
    int t8 = p & 7;
    return (((p >> 3) * 4 + (t8 & 3)) << 2) + (t8 >> 2);
}

// GEMM smem swizzle (uint4 slot 0..7 xor row bits) — proven in R9/R10.
#define SW(s,row) ((s) ^ ((((row)&1)<<2) ^ ((row)&3)))

// ---------------- device scratch (256B-aligned) ----------------
// hi/lo bf16x2 planes, row-major [row][pair]:
__device__ __align__(256) uint32_t g_aqh[M_*NP], g_aql[M_*NP];
__device__ __align__(256) uint32_t g_akh[M_*NP], g_akl[M_*NP];
__device__ __align__(256) uint32_t g_avh[M_*NP], g_avl[M_*NP];
__device__ __align__(256) uint32_t g_aoh[M_*NP], g_aol[M_*NP];
__device__ __align__(256) uint32_t g_wqh[C_*NP], g_wql[C_*NP];
__device__ __align__(256) uint32_t g_wkh[C_*NP], g_wkl[C_*NP];
__device__ __align__(256) uint32_t g_wvh[C_*NP], g_wvl[C_*NP];
__device__ __align__(256) uint32_t g_woh[C_*NP], g_wol[C_*NP];
__device__ __align__(256) float g_q  [M_*C_];            // (b,h,t,d) fp32
__device__ __align__(256) float g_v  [M_*C_];            // (b,h,t,d) fp32
__device__ __align__(256) uint32_t g_kp[BH_*KT*64];      // attention K frags
__device__ __align__(256) uint32_t g_vt[BH_*DH*NKT*64];  // attention V^T frags
__device__ __align__(256) float g_po [BH_*3*QPAD*64];    // attention partial O
__device__ __align__(256) float g_pml[BH_*3*QPAD*2];     // attention partial (m,l)

// ---------------- bf16 mma m16n8k16 + helpers ----------------
__device__ __forceinline__ void mma_bf16(float c[4], const uint32_t a[4],
                                         uint32_t b0, uint32_t b1)
{
    asm volatile(
        "mma.sync.aligned.m16n8k16.row.col.f32.bf16.bf16.f32 "
        "{%0,%1,%2,%3}, {%4,%5,%6,%7}, {%8,%9}, {%0,%1,%2,%3};\n"
        : "+f"(c[0]), "+f"(c[1]), "+f"(c[2]), "+f"(c[3])
        : "r"(a[0]), "r"(a[1]), "r"(a[2]), "r"(a[3]), "r"(b0), "r"(b1));
}

__device__ __forceinline__ void split_pack(float x, float y, uint32_t& hi, uint32_t& lo)
{
    __nv_bfloat162 h = __floats2bfloat162_rn(x, y);
    float xr = x - __bfloat162float(h.x);
    float yr = y - __bfloat162float(h.y);
    __nv_bfloat162 l = __floats2bfloat162_rn(xr, yr);
    hi = *reinterpret_cast<uint32_t*>(&h);
    lo = *reinterpret_cast<uint32_t*>(&l);
}

__device__ __forceinline__ uint32_t pack_hi(float x, float y)
{
    __nv_bfloat162 h = __floats2bfloat162_rn(x, y);
    return *reinterpret_cast<uint32_t*>(&h);
}

__device__ __forceinline__ float ex2(float x)
{
    float y;
    asm("ex2.approx.ftz.f32 %0, %1;" : "=f"(y) : "f"(x));
    return y;
}

// ---------------- kernel 1: dwconv 3x3 + BN -> hi/lo planes ----------------
__global__ void prep_kernel(const float* __restrict__ x,
    const float* __restrict__ kq, const float* __restrict__ kk,
    const float* __restrict__ kv,
    const float* __restrict__ gq, const float* __restrict__ bq,
    const float* __restrict__ mq, const float* __restrict__ vq,
    const float* __restrict__ gk, const float* __restrict__ bk,
    const float* __restrict__ mk, const float* __restrict__ vk,
    const float* __restrict__ gv, const float* __restrict__ bv,
    const float* __restrict__ mv, const float* __restrict__ vv)
{
    int idx = blockIdx.x*blockDim.x + threadIdx.x;
    if (idx >= M_*NP) return;
    int m = idx / NP, pr = idx - m*NP;
    int c = pr*2;
    int t = m % T_, b = m / T_;
    const float* xb = x + (size_t)b*T_*C_;

    float q0, q1, k0, k1, v0, v1;
    if (t == 0) {
        float2 xv = *(const float2*)(xb + c);
        q0 = k0 = v0 = xv.x;
        q1 = k1 = v1 = xv.y;
    } else {
        int p = t - 1, py = p / HW, px = p % HW;
        float aq0=0.f, aq1=0.f, ak0=0.f, ak1=0.f, av0=0.f, av1=0.f;
        #pragma unroll
        for (int dy = 0; dy < 3; dy++) {
            int ny = py + dy - 1;
            if ((unsigned)ny >= (unsigned)HW) continue;
            #pragma unroll
            for (int dx = 0; dx < 3; dx++) {
                int nx = px + dx - 1;
                if ((unsigned)nx >= (unsigned)HW) continue;
                float2 xv = *(const float2*)(xb + (size_t)(1 + ny*HW + nx)*C_ + c);
                int tap = dy*3 + dx;
                aq0 = fmaf(xv.x, kq[c*9+tap],     aq0);
                aq1 = fmaf(xv.y, kq[(c+1)*9+tap], aq1);
                ak0 = fmaf(xv.x, kk[c*9+tap],     ak0);
                ak1 = fmaf(xv.y, kk[(c+1)*9+tap], ak1);
                av0 = fmaf(xv.x, kv[c*9+tap],     av0);
                av1 = fmaf(xv.y, kv[(c+1)*9+tap], av1);
            }
        }
        q0 = (aq0 - mq[c  ]) * (gq[c  ]*rsqrtf(vq[c  ]+BN_EPS)) + bq[c  ];
        q1 = (aq1 - mq[c+1]) * (gq[c+1]*rsqrtf(vq[c+1]+BN_EPS)) + bq[c+1];
        k0 = (ak0 - mk[c  ]) * (gk[c  ]*rsqrtf(vk[c  ]+BN_EPS)) + bk[c  ];
        k1 = (ak1 - mk[c+1]) * (gk[c+1]*rsqrtf(vk[c+1]+BN_EPS)) + bk[c+1];
        v0 = (av0 - mv[c  ]) * (gv[c  ]*rsqrtf(vv[c  ]+BN_EPS)) + bv[c  ];
        v1 = (av1 - mv[c+1]) * (gv[c+1]*rsqrtf(vv[c+1]+BN_EPS)) + bv[c+1];
    }
    uint32_t hi, lo;
    split_pack(q0, q1, hi, lo); g_aqh[idx] = hi; g_aql[idx] = lo;
    split_pack(k0, k1, hi, lo); g_akh[idx] = hi; g_akl[idx] = lo;
    split_pack(v0, v1, hi, lo); g_avh[idx] = hi; g_avl[idx] = lo;
}

// ---------------- weight pre-split -> planes ----------------
__global__ void wsplit(const float* __restrict__ W0, const float* __restrict__ W1,
                       const float* __restrict__ W2, const float* __restrict__ W3,
                       uint32_t* __restrict__ H0, uint32_t* __restrict__ L0,
                       uint32_t* __restrict__ H1, uint32_t* __restrict__ L1,
                       uint32_t* __restrict__ H2, uint32_t* __restrict__ L2,
                       uint32_t* __restrict__ H3, uint32_t* __restrict__ L3)
{
    int idx = blockIdx.x*256 + threadIdx.x;
    if (idx >= C_*NP) return;
    int z = blockIdx.y;
    const float* W = (z==0) ? W0 : (z==1) ? W1 : (z==2) ? W2 : W3;
    uint32_t* Hp   = (z==0) ? H0 : (z==1) ? H1 : (z==2) ? H2 : H3;
    uint32_t* Lp   = (z==0) ? L0 : (z==1) ? L1 : (z==2) ? L2 : L3;
    int n = idx / NP, pr = idx - n*NP;
    float2 v = *(const float2*)(W + (size_t)n*C_ + 2*pr);
    uint32_t hi, lo;
    split_pack(v.x, v.y, hi, lo);
    Hp[idx] = hi; Lp[idx] = lo;
}

// ============ GEMM (round-10 smem format/mma; loaders read planes) ============
#define GEMM_SMEM_DECL \
    __shared__ __align__(16) uint32_t sA[128*32]; \
    __shared__ __align__(16) uint32_t sW[64*32]; \
    uint4* sA4 = reinterpret_cast<uint4*>(sA); \
    uint4* sW4 = reinterpret_cast<uint4*>(sW);

#define LOAD_A(k0off) \
    { \
        int colb = (k0off)/2 + aks*8; \
        if (gm < M_) { \
            rah0 = *(const uint4*)(Ah + (size_t)gm*NP + colb); \
            rah1 = *(const uint4*)(Ah + (size_t)gm*NP + colb + 4); \
            ral0 = *(const uint4*)(Al + (size_t)gm*NP + colb); \
            ral1 = *(const uint4*)(Al + (size_t)gm*NP + colb + 4); \
        } else { \
            rah0 = rah1 = ral0 = ral1 = make_uint4(0,0,0,0); \
        } \
    }

#define LOAD_W(k0off) \
    { \
        int colb = (k0off)/2 + wks*8 + 2*wq; \
        const uint32_t* wbh = Wh + (size_t)(n0 + wrow)*NP + colb; \
        const uint32_t* wbl = Wl + (size_t)(n0 + wrow)*NP + colb; \
        rwh0 = *(const uint2*)(wbh);     rwh1 = *(const uint2*)(wbh + 4); \
        rwl0 = *(const uint2*)(wbl);     rwl1 = *(const uint2*)(wbl + 4); \
    }

#define STORE_A \
    sA4[arow*8 + SW(aks*4+0, arow)] = make_uint4(rah0.x, rah1.x, ral0.x, ral1.x); \
    sA4[arow*8 + SW(aks*4+1, arow)] = make_uint4(rah0.y, rah1.y, ral0.y, ral1.y); \
    sA4[arow*8 + SW(aks*4+2, arow)] = make_uint4(rah0.z, rah1.z, ral0.z, ral1.z); \
    sA4[arow*8 + SW(aks*4+3, arow)] = make_uint4(rah0.w, rah1.w, ral0.w, ral1.w);

#define STORE_W \
    sW4[wrow*8 + SW(wks*4+2*wq,   wrow)] = make_uint4(rwh0.x, rwh1.x, rwl0.x, rwl1.x); \
    sW4[wrow*8 + SW(wks*4+2*wq+1, wrow)] = make_uint4(rwh0.y, rwh1.y, rwl0.y, rwl1.y);

#define GEMM_MMA_BLOCK \
    _Pragma("unroll") \
    for (int ks = 0; ks < 2; ks++) { \
        int fs = ks*4 + tig; \
        uint4 a0 = sA4[(w*16+gid  )*8 + SW(fs, gid)]; \
        uint4 a1 = sA4[(w*16+gid+8)*8 + SW(fs, gid)]; \
        uint32_t ah[4] = {a0.x, a1.x, a0.y, a1.y}; \
        uint32_t al[4] = {a0.z, a1.z, a0.w, a1.w}; \
        _Pragma("unroll") \
        for (int ng = 0; ng < 2; ng++) { \
            uint4 u[4]; \
            _Pragma("unroll") \
            for (int j = 0; j < 4; j++) \
                u[j] = sW4[((ng*4+j)*8+gid)*8 + SW(fs, gid)]; \
            _Pragma("unroll") \
            for (int j = 0; j < 4; j++) mma_bf16(acc[ng*4+j], ah, u[j].x, u[j].y); \
            _Pragma("unroll") \
            for (int j = 0; j < 4; j++) mma_bf16(acc[ng*4+j], ah, u[j].z, u[j].w); \
            _Pragma("unroll") \
            for (int j = 0; j < 4; j++) mma_bf16(acc[ng*4+j], al, u[j].x, u[j].y); \
        } \
    }

#define GEMM_BODY \
    LOAD_A(0) \
    LOAD_W(0) \
    for (int k0 = 0; k0 < C_; k0 += 32) { \
        STORE_A \
        STORE_W \
        __syncthreads(); \
        if (k0 + 32 < C_) { \
            LOAD_A(k0+32) \
            LOAD_W(k0+32) \
        } \
        GEMM_MMA_BLOCK \
        __syncthreads(); \
    }

// ---------------- fused QKV GEMM ----------------
__global__ void __launch_bounds__(256) gemm_qkv(
    const uint32_t* __restrict__ Aqh, const uint32_t* __restrict__ Aql,
    const uint32_t* __restrict__ Akh, const uint32_t* __restrict__ Akl,
    const uint32_t* __restrict__ Avh, const uint32_t* __restrict__ Avl,
    const uint32_t* __restrict__ Wqh, const uint32_t* __restrict__ Wql,
    const uint32_t* __restrict__ Wkh, const uint32_t* __restrict__ Wkl,
    const uint32_t* __restrict__ Wvh, const uint32_t* __restrict__ Wvl,
    float* __restrict__ Dq, float* __restrict__ Dv, uint32_t* __restrict__ Kp)
{
    GEMM_SMEM_DECL
    int z = blockIdx.z;
    const uint32_t* Ah = (z==0) ? Aqh : (z==1) ? Akh : Avh;
    const uint32_t* Al = (z==0) ? Aql : (z==1) ? Akl : Avl;
    const uint32_t* Wh = (z==0) ? Wqh : (z==1) ? Wkh : Wvh;
    const uint32_t* Wl = (z==0) ? Wql : (z==1) ? Wkl : Wvl;
    int m0 = blockIdx.x*128, n0 = blockIdx.y*64;
    int tid = threadIdx.x, w = tid>>5, lane = tid&31;
    int gid = lane>>2, tig = lane&3;
    float acc[8][4] = {};
    int arow = tid>>1, aks = tid&1;
    int wrow = tid>>2, wks = (tid>>1)&1, wq = tid&1;
    int gm = m0 + arow;
    uint4 rah0, rah1, ral0, ral1;
    uint2 rwh0, rwh1, rwl0, rwl1;

    GEMM_BODY

    #pragma unroll
    for (int nt = 0; nt < 8; nt++) {
        int gn = n0 + nt*8 + 2*tig;
        #pragma unroll
        for (int half = 0; half < 2; half++) {
            int gmo = m0 + w*16 + gid + half*8;
            if (gmo >= M_) continue;
            float v0 = acc[nt][half*2+0], v1 = acc[nt][half*2+1];
            int b = gmo / T_, t = gmo % T_;
            int h = gn >> 6, d = gn & 63;
            if (z == 1) {
                uint32_t hi, lo;
                split_pack(v0, v1, hi, lo);
                size_t base = ((size_t)(b*H_ + h)*KT + t)*64;
                int s0 = pslot(d >> 1);
                Kp[base + s0] = hi; Kp[base + s0 + 2] = lo;
            } else {
                float* D = (z==0) ? Dq : Dv;
                float* p = &D[(((size_t)b*H_ + h)*T_ + t)*DH + d];
                p[0] = v0; p[1] = v1;
            }
        }
    }
}

// ---------------- output GEMM (bias) ----------------
__global__ void __launch_bounds__(256) gemm_o(
    const uint32_t* __restrict__ Ah, const uint32_t* __restrict__ Al,
    const uint32_t* __restrict__ Wh, const uint32_t* __restrict__ Wl,
    const float* __restrict__ bias, float* __restrict__ D)
{
    GEMM_SMEM_DECL
    int m0 = blockIdx.x*128, n0 = blockIdx.y*64;
    int tid = threadIdx.x, w = tid>>5, lane = tid&31;
    int gid = lane>>2, tig = lane&3;
    float acc[8][4] = {};
    int arow = tid>>1, aks = tid&1;
    int wrow = tid>>2, wks = (tid>>1)&1, wq = tid&1;
    int gm = m0 + arow;
    uint4 rah0, rah1, ral0, ral1;
    uint2 rwh0, rwh1, rwl0, rwl1;

    GEMM_BODY

    #pragma unroll
    for (int nt = 0; nt < 8; nt++) {
        int gn = n0 + nt*8 + 2*tig;
        #pragma unroll
        for (int half = 0; half < 2; half++) {
            int gmo = m0 + w*16 + gid + half*8;
            if (gmo >= M_) continue;
            float* p = &D[(size_t)gmo*C_ + gn];
            p[0] = acc[nt][half*2+0] + bias[gn];
            p[1] = acc[nt][half*2+1] + bias[gn+1];
        }
    }
}

// ---------------- V transpose + interleaved pack ----------------
__global__ void __launch_bounds__(256) vpack(const float* __restrict__ V,
                                             uint32_t* __restrict__ Vt)
{
    __shared__ float tile[64][36];
    int bh = blockIdx.z, db = blockIdx.y*32, tileidx = blockIdx.x;
    int t0 = tileidx*64;
    int tid = threadIdx.x;
    {
        int tr = tid >> 2;
        int dc = (tid & 3) * 8;
        int gt = t0 + tr;
        if (gt < T_) {
            const float* src = V + ((size_t)bh*T_ + gt)*DH + db + dc;
            *(float4*)&tile[tr][dc]   = *(const float4*)src;
            *(float4*)&tile[tr][dc+4] = *(const float4*)(src + 4);
        } else {
            float4 z = make_float4(0.f,0.f,0.f,0.f);
            *(float4*)&tile[tr][dc]   = z;
            *(float4*)&tile[tr][dc+4] = z;
        }
    }
    __syncthreads();
    {
        int d = tid >> 3;
        int tpc = (tid & 7) * 4;
        size_t base = ((size_t)(bh*DH + db + d)*NKT + tileidx)*64;
        #pragma unroll
        for (int i = 0; i < 4; i++) {
            int p = tpc + i;
            uint32_t hi, lo;
            split_pack(tile[2*p][d], tile[2*p+1][d], hi, lo);
            int s0 = pslot(p);
            Vt[base + s0] = hi; Vt[base + s0 + 2] = lo;
        }
    }
}

// ---------------- flash attention: KV-split x3 (round-10 exact) ----------------
#define QB 128
#define ASTR 80
#define KREG (64*ASTR)
#define BUFU (2*KREG)
#define ATTN_SMEM (2*BUFU*4)
__global__ void __launch_bounds__(256,2) attn_tc2(
    const float* __restrict__ Qh,
    const uint32_t* __restrict__ Kp, const uint32_t* __restrict__ Vt,
    float* __restrict__ po, float* __restrict__ pml)
{
    extern __shared__ uint32_t su[];
    const float SCALE = 0.05103103630798288f * 1.4426950408889634f;
    int bh = blockIdx.y, zt = blockIdx.z;
    int ts = (zt == 0) ? 0 : (zt == 1) ? 12 : 24;
    int te = (zt == 2) ? NKT : ts + 12;
    int q0 = blockIdx.x * QB;
    int tid = threadIdx.x, w = tid>>5, lane = tid&31;
    int gid = lane>>2, tig = lane&3;
    int r0 = q0 + w*16 + gid, r1 = r0 + 8;
    const float* Q = Qh + (size_t)bh*T_*DH;

    uint32_t qfh[4][4], qfl[4][4];
    #pragma unroll
    for (int ks = 0; ks < 4; ks++) {
        int c0 = ks*16 + 2*tig;
        float2 x0 = (r0 < T_) ? *(const float2*)(Q + (size_t)r0*DH + c0    ) : make_float2(0.f,0.f);
        float2 x1 = (r1 < T_) ? *(const float2*)(Q + (size_t)r1*DH + c0    ) : make_float2(0.f,0.f);
        float2 x2 = (r0 < T_) ? *(const float2*)(Q + (size_t)r0*DH + c0 + 8) : make_float2(0.f,0.f);
        float2 x3 = (r1 < T_) ? *(const float2*)(Q + (size_t)r1*DH + c0 + 8) : make_float2(0.f,0.f);
        split_pack(x0.x*SCALE, x0.y*SCALE, qfh[ks][0], qfl[ks][0]);
        split_pack(x1.x*SCALE, x1.y*SCALE, qfh[ks][1], qfl[ks][1]);
        split_pack(x2.x*SCALE, x2.y*SCALE, qfh[ks][2], qfl[ks][2]);
        split_pack(x3.x*SCALE, x3.y*SCALE, qfh[ks][3], qfl[ks][3]);
    }

    uint32_t sb = (uint32_t)__cvta_generic_to_shared(su);
    const uint32_t* gK = Kp + (size_t)bh*KT*64;
    const uint32_t* gV = Vt + (size_t)bh*DH*NKT*64;

    auto issue_tile = [&](int tile, int buf) {
        #pragma unroll
        for (int i = 0; i < 8; i++) {
            int idx = i*256 + tid;
            int arr = idx >> 10;
            int rem = idx & 1023;
            int row = rem >> 4, c4 = (rem & 15) * 4;
            const uint32_t* g = (arr == 0)
                ? gK + ((size_t)(tile*64 + row))*64 + c4
                : gV + ((size_t)row*NKT + tile)*64 + c4;
            uint32_t dst = sb + (buf*BUFU + arr*KREG + row*ASTR + c4)*4;
            asm volatile("cp.async.cg.shared.global [%0], [%1], 16;\n" :: "r"(dst), "l"(g));
        }
        asm volatile("cp.async.commit_group;\n");
    };

    float m0v = -1e30f, m1v = -1e30f, l0 = 0.f, l1 = 0.f;
    float o[8][4] = {};

    issue_tile(ts, 0);

    for (int it = ts; it < te; it++) {
        asm volatile("cp.async.wait_group 0;\n" ::: "memory");
        __syncthreads();
        if (it + 1 < te) issue_tile(it+1, (it+1-ts)&1);

        int buf = (it - ts) & 1;
        const uint4* bK4 = reinterpret_cast<const uint4*>(su + buf*BUFU);
        const uint4* bV4 = reinterpret_cast<const uint4*>(su + buf*BUFU + KREG);

        float s[8][4] = {};
        #pragma unroll
        for (int ks = 0; ks < 4; ks++) {
            #pragma unroll
            for (int ng = 0; ng < 2; ng++) {
                uint4 u[4];
                #pragma unroll
                for (int j = 0; j < 4; j++)
                    u[j] = bK4[((ng*4+j)*8+gid)*(ASTR/4) + ks*4 + tig];
                #pragma unroll
                for (int j = 0; j < 4; j++) mma_bf16(s[ng*4+j], qfh[ks], u[j].x, u[j].y);
                #pragma unroll
                for (int j = 0; j < 4; j++) mma_bf16(s[ng*4+j], qfh[ks], u[j].z, u[j].w);
                #pragma unroll
                for (int j = 0; j < 4; j++) mma_bf16(s[ng*4+j], qfl[ks], u[j].x, u[j].y);
            }
        }

        if (it == NKT-1) {
            int j0 = it*64;
            #pragma unroll
            for (int nt = 0; nt < 8; nt++) {
                int cb = j0 + nt*8 + 2*tig;
                bool c0ok = cb < T_, c1ok = (cb+1) < T_;
                s[nt][0] = c0ok ? s[nt][0] : -1e30f;
                s[nt][1] = c1ok ? s[nt][1] : -1e30f;
                s[nt][2] = c0ok ? s[nt][2] : -1e30f;
                s[nt][3] = c1ok ? s[nt][3] : -1e30f;
            }
        }

        float mx0 = -1e30f, mx1 = -1e30f;
        #pragma unroll
        for (int nt = 0; nt < 8; nt++) {
            mx0 = fmaxf(mx0, fmaxf(s[nt][0], s[nt][1]));
            mx1 = fmaxf(mx1, fmaxf(s[nt][2], s[nt][3]));
        }
        mx0 = fmaxf(mx0, __shfl_xor_sync(0xffffffffu, mx0, 1));
        mx0 = fmaxf(mx0, __shfl_xor_sync(0xffffffffu, mx0, 2));
        mx1 = fmaxf(mx1, __shfl_xor_sync(0xffffffffu, mx1, 1));
        mx1 = fmaxf(mx1, __shfl_xor_sync(0xffffffffu, mx1, 2));

        float m0n = fmaxf(m0v, mx0), m1n = fmaxf(m1v, mx1);
        float a0 = ex2(m0v - m0n), a1 = ex2(m1v - m1n);
        float ps0 = 0.f, ps1 = 0.f;
        #pragma unroll
        for (int nt = 0; nt < 8; nt++) {
            s[nt][0] = ex2(s[nt][0] - m0n);
            s[nt][1] = ex2(s[nt][1] - m0n);
            s[nt][2] = ex2(s[nt][2] - m1n);
            s[nt][3] = ex2(s[nt][3] - m1n);
            ps0 += s[nt][0] + s[nt][1];
            ps1 += s[nt][2] + s[nt][3];
        }
        ps0 += __shfl_xor_sync(0xffffffffu, ps0, 1);
        ps0 += __shfl_xor_sync(0xffffffffu, ps0, 2);
        ps1 += __shfl_xor_sync(0xffffffffu, ps1, 1);
        ps1 += __shfl_xor_sync(0xffffffffu, ps1, 2);
        l0 = l0*a0 + ps0;  m0v = m0n;
        l1 = l1*a1 + ps1;  m1v = m1n;
        #pragma unroll
        for (int nt = 0; nt < 8; nt++) {
            o[nt][0] *= a0; o[nt][1] *= a0;
            o[nt][2] *= a1; o[nt][3] *= a1;
        }

        #pragma unroll
        for (int ks = 0; ks < 4; ks++) {
            uint32_t ah[4];
            ah[0] = pack_hi(s[2*ks  ][0], s[2*ks  ][1]);
            ah[1] = pack_hi(s[2*ks  ][2], s[2*ks  ][3]);
            ah[2] = pack_hi(s[2*ks+1][0], s[2*ks+1][1]);
            ah[3] = pack_hi(s[2*ks+1][2], s[2*ks+1][3]);
            #pragma unroll
            for (int ng = 0; ng < 2; ng++) {
                uint4 u[4];
                #pragma unroll
                for (int j = 0; j < 4; j++)
                    u[j] = bV4[((ng*4+j)*8+gid)*(ASTR/4) + ks*4 + tig];
                #pragma unroll
                for (int j = 0; j < 4; j++) mma_bf16(o[ng*4+j], ah, u[j].x, u[j].y);
                #pragma unroll
                for (int j = 0; j < 4; j++) mma_bf16(o[ng*4+j], ah, u[j].z, u[j].w);
            }
        }
    }

    size_t pbase = (size_t)(bh*3 + zt) * QPAD;
    if (tig == 0) {
        if (r0 < T_) *(float2*)&pml[(pbase + r0)*2] = make_float2(m0v, l0);
        if (r1 < T_) *(float2*)&pml[(pbase + r1)*2] = make_float2(m1v, l1);
    }
    #pragma unroll
    for (int nt = 0; nt < 8; nt++) {
        int d = nt*8 + 2*tig;
        if (r0 < T_)
            *(float2*)&po[(pbase + r0)*64 + d] = make_float2(o[nt][0], o[nt][1]);
        if (r1 < T_)
            *(float2*)&po[(pbase + r1)*64 + d] = make_float2(o[nt][2], o[nt][3]);
    }
}

// ---------------- merge KV-split partials -> hi/lo planes for gemm_o ----------------
__global__ void __launch_bounds__(256) merge_attn(
    const float* __restrict__ po, const float* __restrict__ pml,
    uint32_t* __restrict__ Aoh, uint32_t* __restrict__ Aol)
{
    int idx = blockIdx.x*256 + threadIdx.x;
    if (idx >= BH_*T_*32) return;
    int dp = idx & 31;
    int row = idx >> 5;
    int bh = row / T_, t = row - bh*T_;
    int b = bh / H_, h = bh - b*H_;
    size_t base = (size_t)bh*3*QPAD;
    float2 ml0 = *(const float2*)&pml[(base           + t)*2];
    float2 ml1 = *(const float2*)&pml[(base +   QPAD  + t)*2];
    float2 ml2 = *(const float2*)&pml[(base + 2*QPAD  + t)*2];
    float Mx = fmaxf(ml0.x, fmaxf(ml1.x, ml2.x));
    float w0 = ex2(ml0.x - Mx), w1 = ex2(ml1.x - Mx), w2 = ex2(ml2.x - Mx);
    float invL = 1.0f / (ml0.y*w0 + ml1.y*w1 + ml2.y*w2);
    w0 *= invL; w1 *= invL; w2 *= invL;
    int d = dp*2;
    float2 a0 = *(const float2*)&po[(base          + t)*64 + d];
    float2 a1 = *(const float2*)&po[(base +   QPAD + t)*64 + d];
    float2 a2 = *(const float2*)&po[(base + 2*QPAD + t)*64 + d];
    float o0 = a0.x*w0 + a1.x*w1 + a2.x*w2;
    float o1 = a0.y*w0 + a1.y*w1 + a2.y*w2;
    int m = b*T_ + t;
    int pr = h*32 + dp;
    uint32_t hi, lo;
    split_pack(o0, o1, hi, lo);
    Aoh[(size_t)m*NP + pr] = hi;
    Aol[(size_t)m*NP + pr] = lo;
}

// ---------------- launch ----------------
extern "C" void kernel_launch(void* const* d_in, const int* in_sizes, int n_in,
                              void* d_out, int out_size)
{
    const float* x  = (const float*)d_in[0];
    const float* kq = (const float*)d_in[3];
    const float* kk = (const float*)d_in[4];
    const float* kv = (const float*)d_in[5];
    const float* gq = (const float*)d_in[6];
    const float* bq = (const float*)d_in[7];
    const float* mq = (const float*)d_in[8];
    const float* vq = (const float*)d_in[9];
    const float* gk = (const float*)d_in[10];
    const float* bk = (const float*)d_in[11];
    const float* mk = (const float*)d_in[12];
    const float* vk = (const float*)d_in[13];
    const float* gv = (const float*)d_in[14];
    const float* bv = (const float*)d_in[15];
    const float* mv = (const float*)d_in[16];
    const float* vv = (const float*)d_in[17];
    const float* Wq = (const float*)d_in[18];
    const float* Wk = (const float*)d_in[19];
    const float* Wv = (const float*)d_in[20];
    const float* Wo = (const float*)d_in[21];
    const float* bo = (const float*)d_in[22];
    float* out = (float*)d_out;

    float *qh, *vh, *po, *pml;
    uint32_t *aqh,*aql,*akh,*akl,*avh,*avl,*aoh,*aol;
    uint32_t *wqh,*wql,*wkh,*wkl,*wvh,*wvl,*woh,*wol;
    uint32_t *kp, *vt;
    cudaGetSymbolAddress((void**)&aqh, g_aqh); cudaGetSymbolAddress((void**)&aql, g_aql);
    cudaGetSymbolAddress((void**)&akh, g_akh); cudaGetSymbolAddress((void**)&akl, g_akl);
    cudaGetSymbolAddress((void**)&avh, g_avh); cudaGetSymbolAddress((void**)&avl, g_avl);
    cudaGetSymbolAddress((void**)&aoh, g_aoh); cudaGetSymbolAddress((void**)&aol, g_aol);
    cudaGetSymbolAddress((void**)&wqh, g_wqh); cudaGetSymbolAddress((void**)&wql, g_wql);
    cudaGetSymbolAddress((void**)&wkh, g_wkh); cudaGetSymbolAddress((void**)&wkl, g_wkl);
    cudaGetSymbolAddress((void**)&wvh, g_wvh); cudaGetSymbolAddress((void**)&wvl, g_wvl);
    cudaGetSymbolAddress((void**)&woh, g_woh); cudaGetSymbolAddress((void**)&wol, g_wol);
    cudaGetSymbolAddress((void**)&qh,  g_q);
    cudaGetSymbolAddress((void**)&vh,  g_v);
    cudaGetSymbolAddress((void**)&kp,  g_kp);
    cudaGetSymbolAddress((void**)&vt,  g_vt);
    cudaGetSymbolAddress((void**)&po,  g_po);
    cudaGetSymbolAddress((void**)&pml, g_pml);

    prep_kernel<<<(M_*NP + 255)/256, 256>>>(x, kq, kk, kv,
                                            gq, bq, mq, vq,
                                            gk, bk, mk, vk,
                                            gv, bv, mv, vv);

    wsplit<<<dim3((C_*NP + 255)/256, 4), 256>>>(Wq, Wk, Wv, Wo,
                                                wqh, wql, wkh, wkl,
                                                wvh, wvl, woh, wol);

    dim3 gq3((M_ + 127)/128, C_/64, 3);
    gemm_qkv<<<gq3, 256>>>(aqh, aql, akh, akl, avh, avl,
                           wqh, wql, wkh, wkl, wvh, wvl,
                           qh, vh, kp);

    vpack<<<dim3(NKT, DH/32, BH_), 256>>>(vh, vt);

    cudaFuncSetAttribute(attn_tc2,
                         cudaFuncAttributeMaxDynamicSharedMemorySize, ATTN_SMEM);
    attn_tc2<<<dim3((T_ + QB - 1)/QB, BH_, 3), 256, ATTN_SMEM>>>(qh, kp, vt, po, pml);

    merge_attn<<<(BH_*T_*32 + 255)/256, 256>>>(po, pml, aoh, aol);

    gemm_o<<<dim3((M_ + 127)/128, C_/64), 256>>>(aoh, aol, woh, wol, bo, out);
}

// round 15
// speedup vs baseline: 1.0260x; 1.0260x over previous
#include <cuda_runtime.h>
#include <cuda_bf16.h>
#include <math.h>
#include <stdint.h>

#define B_  4
#define T_  2305
#define C_  384
#define H_  6
#define BH_ (B_*H_)          // 24
#define DH  64
#define HW  48
#define M_  (B_*T_)          // 9220 rows
#define BN_EPS 1e-5f
#define NKT 37               // key tiles of 64
#define KT  (NKT*64)         // 2368 padded keys
#define QPAD 2432            // 19*128 padded queries

// Attention interleaved fragment layout (global K/V), unchanged since R8.
__device__ __forceinline__ int pslot(int p)   // returns hi slot (pair lo = +2)
{
    int t8 = p & 7;
    return (((p >> 3) * 4 + (t8 & 3)) << 2) + (t8 >> 2);
}

// GEMM smem swizzle (uint4 slot 0..7 xor row bits) — proven R9/R10.
#define SW(s,row) ((s) ^ ((((row)&1)<<2) ^ ((row)&3)))

// ---------------- device scratch (256B-aligned) ----------------
__device__ __align__(256) float g_qin[M_*C_];
__device__ __align__(256) float g_kin[M_*C_];
__device__ __align__(256) float g_vin[M_*C_];
__device__ __align__(256) float g_q  [M_*C_];            // (b,h,t,d) fp32
__device__ __align__(256) float g_v  [M_*C_];            // (b,h,t,d) fp32
__device__ __align__(256) uint32_t g_kp[BH_*KT*64];      // attention K frags
__device__ __align__(256) uint32_t g_vt[BH_*DH*NKT*64];  // attention V^T frags
__device__ __align__(256) float g_att[M_*C_];            // (b,t,c)
__device__ __align__(256) float g_po [BH_*3*QPAD*64];    // attention partial O
__device__ __align__(256) float g_pml[BH_*3*QPAD*2];     // attention partial (m,l)
__device__ __align__(256) float g_sq[C_], g_sk[C_], g_sv[C_];   // BN scales

// ---------------- bf16 mma m16n8k16 + helpers ----------------
__device__ __forceinline__ void mma_bf16(float c[4], const uint32_t a[4],
                                         uint32_t b0, uint32_t b1)
{
    asm volatile(
        "mma.sync.aligned.m16n8k16.row.col.f32.bf16.bf16.f32 "
        "{%0,%1,%2,%3}, {%4,%5,%6,%7}, {%8,%9}, {%0,%1,%2,%3};\n"
        : "+f"(c[0]), "+f"(c[1]), "+f"(c[2]), "+f"(c[3])
        : "r"(a[0]), "r"(a[1]), "r"(a[2]), "r"(a[3]), "r"(b0), "r"(b1));
}

__device__ __forceinline__ void split_pack(float x, float y, uint32_t& hi, uint32_t& lo)
{
    __nv_bfloat162 h = __floats2bfloat162_rn(x, y);
    float xr = x - __bfloat162float(h.x);
    float yr = y - __bfloat162float(h.y);
    __nv_bfloat162 l = __floats2bfloat162_rn(xr, yr);
    hi = *reinterpret_cast<uint32_t*>(&h);
    lo = *reinterpret_cast<uint32_t*>(&l);
}

__device__ __forceinline__ uint32_t pack_hi(float x, float y)
{
    __nv_bfloat162 h = __floats2bfloat162_rn(x, y);
    return *reinterpret_cast<uint32_t*>(&h);
}

__device__ __forceinline__ float ex2(float x)
{
    float y;
    asm("ex2.approx.ftz.f32 %0, %1;" : "=f"(y) : "f"(x));
    return y;
}

// ---------------- kernel 0: BN scale precompute (bit-identical expr) ----------------
__global__ void bnscale(const float* __restrict__ gq, const float* __restrict__ vq,
                        const float* __restrict__ gk, const float* __restrict__ vk,
                        const float* __restrict__ gv, const float* __restrict__ vv)
{
    int c = threadIdx.x;
    if (c < C_) {
        g_sq[c] = gq[c]*rsqrtf(vq[c]+BN_EPS);
        g_sk[c] = gk[c]*rsqrtf(vk[c]+BN_EPS);
        g_sv[c] = gv[c]*rsqrtf(vv[c]+BN_EPS);
    }
}

// ---------------- kernel 1: depthwise conv 3x3 + BN (scales preloaded) ----------------
__global__ void prep_kernel(const float* __restrict__ x,
    const float* __restrict__ kq, const float* __restrict__ kk,
    const float* __restrict__ kv,
    const float* __restrict__ bq, const float* __restrict__ mq,
    const float* __restrict__ bk, const float* __restrict__ mk,
    const float* __restrict__ bv, const float* __restrict__ mv)
{
    int idx = blockIdx.x*blockDim.x + threadIdx.x;
    if (idx >= M_*C_) return;
    int c = idx % C_;
    int t = (idx / C_) % T_;
    int b = idx / (C_*T_);
    const float* xb = x + (size_t)b*T_*C_;
    if (t == 0) {
        float v = xb[c];
        g_qin[idx] = v; g_kin[idx] = v; g_vin[idx] = v;
        return;
    }
    int p = t - 1, py = p / HW, px = p % HW;
    float aq = 0.f, ak = 0.f, av = 0.f;
    #pragma unroll
    for (int dy = 0; dy < 3; dy++) {
        int ny = py + dy - 1;
        if ((unsigned)ny >= (unsigned)HW) continue;
        #pragma unroll
        for (int dx = 0; dx < 3; dx++) {
            int nx = px + dx - 1;
            if ((unsigned)nx >= (unsigned)HW) continue;
            float xv = xb[(size_t)(1 + ny*HW + nx)*C_ + c];
            int tap = dy*3 + dx;
            aq = fmaf(xv, kq[c*9 + tap], aq);
            ak = fmaf(xv, kk[c*9 + tap], ak);
            av = fmaf(xv, kv[c*9 + tap], av);
        }
    }
    g_qin[idx] = (aq - mq[c]) * g_sq[c] + bq[c];
    g_kin[idx] = (ak - mk[c]) * g_sk[c] + bk[c];
    g_vin[idx] = (av - mv[c]) * g_sv[c] + bv[c];
}

// ============ GEMM building blocks (round-10, proven) ============
#define GEMM_SMEM_DECL \
    __shared__ __align__(16) uint32_t sA[128*32]; \
    __shared__ __align__(16) uint32_t sW[64*32]; \
    uint4* sA4 = reinterpret_cast<uint4*>(sA); \
    uint4* sW4 = reinterpret_cast<uint4*>(sW);

#define GEMM_STORE_A \
    _Pragma("unroll") \
    for (int tg = 0; tg < 4; tg++) { \
        float x0, x1, y0, y1; \
        if (tg & 1) { x0 = ra[tg>>1].z; x1 = ra[tg>>1].w; \
                      y0 = ra[2+(tg>>1)].z; y1 = ra[2+(tg>>1)].w; } \
        else        { x0 = ra[tg>>1].x; x1 = ra[tg>>1].y; \
                      y0 = ra[2+(tg>>1)].x; y1 = ra[2+(tg>>1)].y; } \
        uint32_t hA, lA, hB, lB; \
        split_pack(x0, x1, hA, lA); \
        split_pack(y0, y1, hB, lB); \
        sA4[arow*8 + SW(aks*4 + tg, arow)] = make_uint4(hA, hB, lA, lB); \
    }

#define GEMM_STORE_W \
    _Pragma("unroll") \
    for (int j = 0; j < 2; j++) { \
        float x0 = j ? rw0.z : rw0.x, x1 = j ? rw0.w : rw0.y; \
        float y0 = j ? rw1.z : rw1.x, y1 = j ? rw1.w : rw1.y; \
        uint32_t hA, lA, hB, lB; \
        split_pack(x0, x1, hA, lA); \
        split_pack(y0, y1, hB, lB); \
        int tg = 2*wq + j; \
        sW4[wrow*8 + SW(wks*4 + tg, wrow)] = make_uint4(hA, hB, lA, lB); \
    }

#define GEMM_MMA_BLOCK \
    _Pragma("unroll") \
    for (int ks = 0; ks < 2; ks++) { \
        int fs = ks*4 + tig; \
        uint4 a0 = sA4[(w*16+gid  )*8 + SW(fs, gid)]; \
        uint4 a1 = sA4[(w*16+gid+8)*8 + SW(fs, gid)]; \
        uint32_t ah[4] = {a0.x, a1.x, a0.y, a1.y}; \
        uint32_t al[4] = {a0.z, a1.z, a0.w, a1.w}; \
        _Pragma("unroll") \
        for (int ng = 0; ng < 2; ng++) { \
            uint4 u[4]; \
            _Pragma("unroll") \
            for (int j = 0; j < 4; j++) \
                u[j] = sW4[((ng*4+j)*8+gid)*8 + SW(fs, gid)]; \
            _Pragma("unroll") \
            for (int j = 0; j < 4; j++) mma_bf16(acc[ng*4+j], ah, u[j].x, u[j].y); \
            _Pragma("unroll") \
            for (int j = 0; j < 4; j++) mma_bf16(acc[ng*4+j], ah, u[j].z, u[j].w); \
            _Pragma("unroll") \
            for (int j = 0; j < 4; j++) mma_bf16(acc[ng*4+j], al, u[j].x, u[j].y); \
        } \
    }

#define GEMM_LOAD_W(k0off) \
    rw0 = *(const float4*)(W + (size_t)(n0 + wrow)*C_ + (k0off) + wks*16 + wq*4); \
    rw1 = *(const float4*)(W + (size_t)(n0 + wrow)*C_ + (k0off) + wks*16 + wq*4 + 8);

// ---------------- fused QKV GEMM (round-10 exact) ----------------
__global__ void __launch_bounds__(256) gemm_qkv(
    const float* __restrict__ Aq, const float* __restrict__ Ak, const float* __restrict__ Av,
    const float* __restrict__ Wq, const float* __restrict__ Wk, const float* __restrict__ Wv,
    float* __restrict__ Dq, float* __restrict__ Dv, uint32_t* __restrict__ Kp)
{
    GEMM_SMEM_DECL
    int z = blockIdx.z;
    const float* A = (z==0) ? Aq : (z==1) ? Ak : Av;
    const float* W = (z==0) ? Wq : (z==1) ? Wk : Wv;
    int m0 = blockIdx.x*128, n0 = blockIdx.y*64;
    int tid = threadIdx.x, w = tid>>5, lane = tid&31;
    int gid = lane>>2, tig = lane&3;
    float acc[8][4] = {};
    int arow = tid>>1, aks = tid&1;
    int wrow = tid>>2, wks = (tid>>1)&1, wq = tid&1;
    int gm = m0 + arow;

    float4 ra[4], rw0, rw1;
    #pragma unroll
    for (int i = 0; i < 4; i++)
        ra[i] = (gm < M_) ? *(const float4*)(A + (size_t)gm*C_ + aks*16 + i*4)
                          : make_float4(0.f,0.f,0.f,0.f);
    GEMM_LOAD_W(0)

    for (int k0 = 0; k0 < C_; k0 += 32) {
        GEMM_STORE_A
        GEMM_STORE_W
        __syncthreads();
        if (k0 + 32 < C_) {
            #pragma unroll
            for (int i = 0; i < 4; i++)
                ra[i] = (gm < M_) ? *(const float4*)(A + (size_t)gm*C_ + k0+32 + aks*16 + i*4)
                                  : make_float4(0.f,0.f,0.f,0.f);
            GEMM_LOAD_W(k0+32)
        }
        GEMM_MMA_BLOCK
        __syncthreads();
    }

    #pragma unroll
    for (int nt = 0; nt < 8; nt++) {
        int gn = n0 + nt*8 + 2*tig;
        #pragma unroll
        for (int half = 0; half < 2; half++) {
            int gmo = m0 + w*16 + gid + half*8;
            if (gmo >= M_) continue;
            float v0 = acc[nt][half*2+0], v1 = acc[nt][half*2+1];
            int b = gmo / T_, t = gmo % T_;
            int h = gn >> 6, d = gn & 63;
            if (z == 1) {
                uint32_t hi, lo;
                split_pack(v0, v1, hi, lo);
                size_t base = ((size_t)(b*H_ + h)*KT + t)*64;
                int s0 = pslot(d >> 1);
                Kp[base + s0] = hi; Kp[base + s0 + 2] = lo;
            } else {
                float* D = (z==0) ? Dq : Dv;
                float* p = &D[(((size_t)b*H_ + h)*T_ + t)*DH + d];
                p[0] = v0; p[1] = v1;
            }
        }
    }
}

// ---------------- output GEMM (round-10 exact, bias) ----------------
__global__ void __launch_bounds__(256) gemm_o(
    const float* __restrict__ A, const float* __restrict__ W,
    const float* __restrict__ bias, float* __restrict__ D)
{
    GEMM_SMEM_DECL
    int m0 = blockIdx.x*128, n0 = blockIdx.y*64;
    int tid = threadIdx.x, w = tid>>5, lane = tid&31;
    int gid = lane>>2, tig = lane&3;
    float acc[8][4] = {};
    int arow = tid>>1, aks = tid&1;
    int wrow = tid>>2, wks = (tid>>1)&1, wq = tid&1;
    int gm = m0 + arow;

    float4 ra[4], rw0, rw1;
    #pragma unroll
    for (int i = 0; i < 4; i++)
        ra[i] = (gm < M_) ? *(const float4*)(A + (size_t)gm*C_ + aks*16 + i*4)
                          : make_float4(0.f,0.f,0.f,0.f);
    GEMM_LOAD_W(0)

    for (int k0 = 0; k0 < C_; k0 += 32) {
        GEMM_STORE_A
        GEMM_STORE_W
        __syncthreads();
        if (k0 + 32 < C_) {
            #pragma unroll
            for (int i = 0; i < 4; i++)
                ra[i] = (gm < M_) ? *(const float4*)(A + (size_t)gm*C_ + k0+32 + aks*16 + i*4)
                                  : make_float4(0.f,0.f,0.f,0.f);
            GEMM_LOAD_W(k0+32)
        }
        GEMM_MMA_BLOCK
        __syncthreads();
    }

    #pragma unroll
    for (int nt = 0; nt < 8; nt++) {
        int gn = n0 + nt*8 + 2*tig;
        #pragma unroll
        for (int half = 0; half < 2; half++) {
            int gmo = m0 + w*16 + gid + half*8;
            if (gmo >= M_) continue;
            float* p = &D[(size_t)gmo*C_ + gn];
            p[0] = acc[nt][half*2+0] + bias[gn];
            p[1] = acc[nt][half*2+1] + bias[gn+1];
        }
    }
}

// ---------------- V transpose + interleaved pack ----------------
__global__ void __launch_bounds__(256) vpack(const float* __restrict__ V,
                                             uint32_t* __restrict__ Vt)
{
    __shared__ float tile[64][36];
    int bh = blockIdx.z, db = blockIdx.y*32, tileidx = blockIdx.x;
    int t0 = tileidx*64;
    int tid = threadIdx.x;
    {
        int tr = tid >> 2;
        int dc = (tid & 3) * 8;
        int gt = t0 + tr;
        if (gt < T_) {
            const float* src = V + ((size_t)bh*T_ + gt)*DH + db + dc;
            *(float4*)&tile[tr][dc]   = *(const float4*)src;
            *(float4*)&tile[tr][dc+4] = *(const float4*)(src + 4);
        } else {
            float4 z = make_float4(0.f,0.f,0.f,0.f);
            *(float4*)&tile[tr][dc]   = z;
            *(float4*)&tile[tr][dc+4] = z;
        }
    }
    __syncthreads();
    {
        int d = tid >> 3;
        int tpc = (tid & 7) * 4;
        size_t base = ((size_t)(bh*DH + db + d)*NKT + tileidx)*64;
        #pragma unroll
        for (int i = 0; i < 4; i++) {
            int p = tpc + i;
            uint32_t hi, lo;
            split_pack(tile[2*p][d], tile[2*p+1][d], hi, lo);
            int s0 = pslot(p);
            Vt[base + s0] = hi; Vt[base + s0 + 2] = lo;
        }
    }
}

// ---------------- flash attention: KV-split {13,12,12} ----------------
#define QB 128
#define ASTR 80
#define KREG (64*ASTR)
#define BUFU (2*KREG)
#define ATTN_SMEM (2*BUFU*4)
__global__ void __launch_bounds__(256,2) attn_tc2(
    const float* __restrict__ Qh,
    const uint32_t* __restrict__ Kp, const uint32_t* __restrict__ Vt,
    float* __restrict__ po, float* __restrict__ pml)
{
    extern __shared__ uint32_t su[];
    const float SCALE = 0.05103103630798288f * 1.4426950408889634f;
    int bh = blockIdx.y, zt = blockIdx.z;
    int ts = (zt == 0) ? 0 : (zt == 1) ? 13 : 25;
    int te = (zt == 0) ? 13 : (zt == 1) ? 25 : NKT;
    int q0 = blockIdx.x * QB;
    int tid = threadIdx.x, w = tid>>5, lane = tid&31;
    int gid = lane>>2, tig = lane&3;
    int r0 = q0 + w*16 + gid, r1 = r0 + 8;
    const float* Q = Qh + (size_t)bh*T_*DH;

    uint32_t qfh[4][4], qfl[4][4];
    #pragma unroll
    for (int ks = 0; ks < 4; ks++) {
        int c0 = ks*16 + 2*tig;
        float2 x0 = (r0 < T_) ? *(const float2*)(Q + (size_t)r0*DH + c0    ) : make_float2(0.f,0.f);
        float2 x1 = (r1 < T_) ? *(const float2*)(Q + (size_t)r1*DH + c0    ) : make_float2(0.f,0.f);
        float2 x2 = (r0 < T_) ? *(const float2*)(Q + (size_t)r0*DH + c0 + 8) : make_float2(0.f,0.f);
        float2 x3 = (r1 < T_) ? *(const float2*)(Q + (size_t)r1*DH + c0 + 8) : make_float2(0.f,0.f);
        split_pack(x0.x*SCALE, x0.y*SCALE, qfh[ks][0], qfl[ks][0]);
        split_pack(x1.x*SCALE, x1.y*SCALE, qfh[ks][1], qfl[ks][1]);
        split_pack(x2.x*SCALE, x2.y*SCALE, qfh[ks][2], qfl[ks][2]);
        split_pack(x3.x*SCALE, x3.y*SCALE, qfh[ks][3], qfl[ks][3]);
    }

    uint32_t sb = (uint32_t)__cvta_generic_to_shared(su);
    const uint32_t* gK = Kp + (size_t)bh*KT*64;
    const uint32_t* gV = Vt + (size_t)bh*DH*NKT*64;

    auto issue_tile = [&](int tile, int buf) {
        #pragma unroll
        for (int i = 0; i < 8; i++) {
            int idx = i*256 + tid;
            int arr = idx >> 10;
            int rem = idx & 1023;
            int row = rem >> 4, c4 = (rem & 15) * 4;
            const uint32_t* g = (arr == 0)
                ? gK + ((size_t)(tile*64 + row))*64 + c4
                : gV + ((size_t)row*NKT + tile)*64 + c4;
            uint32_t dst = sb + (buf*BUFU + arr*KREG + row*ASTR + c4)*4;
            asm volatile("cp.async.cg.shared.global [%0], [%1], 16;\n" :: "r"(dst), "l"(g));
        }
        asm volatile("cp.async.commit_group;\n");
    };

    float m0v = -1e30f, m1v = -1e30f, l0 = 0.f, l1 = 0.f;
    float o[8][4] = {};

    issue_tile(ts, 0);

    for (int it = ts; it < te; it++) {
        asm volatile("cp.async.wait_group 0;\n" ::: "memory");
        __syncthreads();
        if (it + 1 < te) issue_tile(it+1, (it+1-ts)&1);

        int buf = (it - ts) & 1;
        const uint4* bK4 = reinterpret_cast<const uint4*>(su + buf*BUFU);
        const uint4* bV4 = reinterpret_cast<const uint4*>(su + buf*BUFU + KREG);

        float s[8][4] = {};
        #pragma unroll
        for (int ks = 0; ks < 4; ks++) {
            #pragma unroll
            for (int ng = 0; ng < 2; ng++) {
                uint4 u[4];
                #pragma unroll
                for (int j = 0; j < 4; j++)
                    u[j] = bK4[((ng*4+j)*8+gid)*(ASTR/4) + ks*4 + tig];
                #pragma unroll
                for (int j = 0; j < 4; j++) mma_bf16(s[ng*4+j], qfh[ks], u[j].x, u[j].y);
                #pragma unroll
                for (int j = 0; j < 4; j++) mma_bf16(s[ng*4+j], qfh[ks], u[j].z, u[j].w);
                #pragma unroll
                for (int j = 0; j < 4; j++) mma_bf16(s[ng*4+j], qfl[ks], u[j].x, u[j].y);
            }
        }

        if (it == NKT-1) {
            int j0 = it*64;
            #pragma unroll
            for (int nt = 0; nt < 8; nt++) {
                int cb = j0 + nt*8 + 2*tig;
                bool c0ok = cb < T_, c1ok = (cb+1) < T_;
                s[nt][0] = c0ok ? s[nt][0] : -1e30f;
                s[nt][1] = c1ok ? s[nt][1] : -1e30f;
                s[nt][2] = c0ok ? s[nt][2] : -1e30f;
                s[nt][3] = c1ok ? s[nt][3] : -1e30f;
            }
        }

        float mx0 = -1e30f, mx1 = -1e30f;
        #pragma unroll
        for (int nt = 0; nt < 8; nt++) {
            mx0 = fmaxf(mx0, fmaxf(s[nt][0], s[nt][1]));
            mx1 = fmaxf(mx1, fmaxf(s[nt][2], s[nt][3]));
        }
        mx0 = fmaxf(mx0, __shfl_xor_sync(0xffffffffu, mx0, 1));
        mx0 = fmaxf(mx0, __shfl_xor_sync(0xffffffffu, mx0, 2));
        mx1 = fmaxf(mx1, __shfl_xor_sync(0xffffffffu, mx1, 1));
        mx1 = fmaxf(mx1, __shfl_xor_sync(0xffffffffu, mx1, 2));

        float m0n = fmaxf(m0v, mx0), m1n = fmaxf(m1v, mx1);
        float a0 = ex2(m0v - m0n), a1 = ex2(m1v - m1n);
        float ps0 = 0.f, ps1 = 0.f;
        #pragma unroll
        for (int nt = 0; nt < 8; nt++) {
            s[nt][0] = ex2(s[nt][0] - m0n);
            s[nt][1] = ex2(s[nt][1] - m0n);
            s[nt][2] = ex2(s[nt][2] - m1n);
            s[nt][3] = ex2(s[nt][3] - m1n);
            ps0 += s[nt][0] + s[nt][1];
            ps1 += s[nt][2] + s[nt][3];
        }
        ps0 += __shfl_xor_sync(0xffffffffu, ps0, 1);
        ps0 += __shfl_xor_sync(0xffffffffu, ps0, 2);
        ps1 += __shfl_xor_sync(0xffffffffu, ps1, 1);
        ps1 += __shfl_xor_sync(0xffffffffu, ps1, 2);
        l0 = l0*a0 + ps0;  m0v = m0n;
        l1 = l1*a1 + ps1;  m1v = m1n;
        #pragma unroll
        for (int nt = 0; nt < 8; nt++) {
            o[nt][0] *= a0; o[nt][1] *= a0;
            o[nt][2] *= a1; o[nt][3] *= a1;
        }

        #pragma unroll
        for (int ks = 0; ks < 4; ks++) {
            uint32_t ah[4];
            ah[0] = pack_hi(s[2*ks  ][0], s[2*ks  ][1]);
            ah[1] = pack_hi(s[2*ks  ][2], s[2*ks  ][3]);
            ah[2] = pack_hi(s[2*ks+1][0], s[2*ks+1][1]);
            ah[3] = pack_hi(s[2*ks+1][2], s[2*ks+1][3]);
            #pragma unroll
            for (int ng = 0; ng < 2; ng++) {
                uint4 u[4];
                #pragma unroll
                for (int j = 0; j < 4; j++)
                    u[j] = bV4[((ng*4+j)*8+gid)*(ASTR/4) + ks*4 + tig];
                #pragma unroll
                for (int j = 0; j < 4; j++) mma_bf16(o[ng*4+j], ah, u[j].x, u[j].y);
                #pragma unroll
                for (int j = 0; j < 4; j++) mma_bf16(o[ng*4+j], ah, u[j].z, u[j].w);
            }
        }
    }

    size_t pbase = (size_t)(bh*3 + zt) * QPAD;
    if (tig == 0) {
        if (r0 < T_) *(float2*)&pml[(pbase + r0)*2] = make_float2(m0v, l0);
        if (r1 < T_) *(float2*)&pml[(pbase + r1)*2] = make_float2(m1v, l1);
    }
    #pragma unroll
    for (int nt = 0; nt < 8; nt++) {
        int d = nt*8 + 2*tig;
        if (r0 < T_)
            *(float2*)&po[(pbase + r0)*64 + d] = make_float2(o[nt][0], o[nt][1]);
        if (r1 < T_)
            *(float2*)&po[(pbase + r1)*64 + d] = make_float2(o[nt][2], o[nt][3]);
    }
}

// ---------------- merge KV-split partials ----------------
__global__ void __launch_bounds__(256) merge_attn(
    const float* __restrict__ po, const float* __restrict__ pml,
    float* __restrict__ Oa)
{
    int idx = blockIdx.x*256 + threadIdx.x;
    if (idx >= BH_*T_*64) return;
    int d = idx & 63;
    int row = idx >> 6;
    int bh = row / T_, t = row - bh*T_;
    int b = bh / H_, h = bh - b*H_;
    size_t base = (size_t)bh*3*QPAD;
    float2 ml0 = *(const float2*)&pml[(base           + t)*2];
    float2 ml1 = *(const float2*)&pml[(base +   QPAD  + t)*2];
    float2 ml2 = *(const float2*)&pml[(base + 2*QPAD  + t)*2];
    float M = fmaxf(ml0.x, fmaxf(ml1.x, ml2.x));
    float w0 = ex2(ml0.x - M), w1 = ex2(ml1.x - M), w2 = ex2(ml2.x - M);
    float L = ml0.y*w0 + ml1.y*w1 + ml2.y*w2;
    float ov = po[(base          + t)*64 + d]*w0
             + po[(base +   QPAD + t)*64 + d]*w1
             + po[(base + 2*QPAD + t)*64 + d]*w2;
    Oa[((size_t)b*T_ + t)*C_ + h*DH + d] = ov / L;
}

// ---------------- launch ----------------
extern "C" void kernel_launch(void* const* d_in, const int* in_sizes, int n_in,
                              void* d_out, int out_size)
{
    const float* x  = (const float*)d_in[0];
    const float* kq = (const float*)d_in[3];
    const float* kk = (const float*)d_in[4];
    const float* kv = (const float*)d_in[5];
    const float* gq = (const float*)d_in[6];
    const float* bq = (const float*)d_in[7];
    const float* mq = (const float*)d_in[8];
    const float* vq = (const float*)d_in[9];
    const float* gk = (const float*)d_in[10];
    const float* bk = (const float*)d_in[11];
    const float* mk = (const float*)d_in[12];
    const float* vk = (const float*)d_in[13];
    const float* gv = (const float*)d_in[14];
    const float* bv = (const float*)d_in[15];
    const float* mv = (const float*)d_in[16];
    const float* vv = (const float*)d_in[17];
    const float* Wq = (const float*)d_in[18];
    const float* Wk = (const float*)d_in[19];
    const float* Wv = (const float*)d_in[20];
    const float* Wo = (const float*)d_in[21];
    const float* bo = (const float*)d_in[22];
    float* out = (float*)d_out;

    float *qin, *kin, *vin, *qh, *vh, *att, *po, *pml;
    uint32_t *kp, *vt;
    cudaGetSymbolAddress((void**)&qin, g_qin);
    cudaGetSymbolAddress((void**)&kin, g_kin);
    cudaGetSymbolAddress((void**)&vin, g_vin);
    cudaGetSymbolAddress((void**)&qh,  g_q);
    cudaGetSymbolAddress((void**)&vh,  g_v);
    cudaGetSymbolAddress((void**)&att, g_att);
    cudaGetSymbolAddress((void**)&kp,  g_kp);
    cudaGetSymbolAddress((void**)&vt,  g_vt);
    cudaGetSymbolAddress((void**)&po,  g_po);
    cudaGetSymbolAddress((void**)&pml, g_pml);

    bnscale<<<1, 384>>>(gq, vq, gk, vk, gv, vv);

    prep_kernel<<<(M_*C_ + 255)/256, 256>>>(x, kq, kk, kv,
                                            bq, mq, bk, mk, bv, mv);

    dim3 gq3((M_ + 127)/128, C_/64, 3);
    gemm_qkv<<<gq3, 256>>>(qin, kin, vin, Wq, Wk, Wv, qh, vh, kp);

    vpack<<<dim3(NKT, DH/32, BH_), 256>>>(vh, vt);

    cudaFuncSetAttribute(attn_tc2,
                         cudaFuncAttributeMaxDynamicSharedMemorySize, ATTN_SMEM);
    attn_tc2<<<dim3((T_ + QB - 1)/QB, BH_, 3), 256, ATTN_SMEM>>>(qh, kp, vt, po, pml);

    merge_attn<<<(BH_*T_*64 + 255)/256, 256>>>(po, pml, att);

    gemm_o<<<dim3((M_ + 127)/128, C_/64), 256>>>(att, Wo, bo, out);
}

// round 16
// speedup vs baseline: 1.1261x; 1.0975x over previous
#include <cuda_runtime.h>
#include <cuda_bf16.h>
#include <math.h>
#include <stdint.h>

#define B_  4
#define T_  2305
#define C_  384
#define H_  6
#define BH_ (B_*H_)          // 24
#define DH  64
#define HW  48
#define M_  (B_*T_)          // 9220 rows
#define BN_EPS 1e-5f
#define NKT 37               // key tiles of 64
#define KT  (NKT*64)         // 2368 padded keys
#define QPAD 2432            // 19*128 padded queries

// Attention interleaved fragment layout (global K/V), unchanged since R8.
__device__ __forceinline__ int pslot(int p)   // returns hi slot (pair lo = +2)
{
    int t8 = p & 7;
    return (((p >> 3) * 4 + (t8 & 3)) << 2) + (t8 >> 2);
}

// GEMM smem swizzle (uint4 slot 0..7 xor row bits) — proven R9/R10.
#define SW(s,row) ((s) ^ ((((row)&1)<<2) ^ ((row)&3)))

// ---------------- device scratch (256B-aligned) ----------------
__device__ __align__(256) float g_qin[M_*C_];
__device__ __align__(256) float g_kin[M_*C_];
__device__ __align__(256) float g_vin[M_*C_];
__device__ __align__(256) float g_q  [M_*C_];            // (b,h,t,d) fp32
__device__ __align__(256) float g_v  [M_*C_];            // (b,h,t,d) fp32
__device__ __align__(256) uint32_t g_kp[BH_*KT*64];      // attention K frags
__device__ __align__(256) uint32_t g_vt[BH_*DH*NKT*64];  // attention V^T frags
__device__ __align__(256) float g_att[M_*C_];            // (b,t,c)
__device__ __align__(256) float g_po [BH_*3*QPAD*64];    // attention partial O
__device__ __align__(256) float g_pml[BH_*3*QPAD*2];     // attention partial (m,l)

// ---------------- bf16 mma m16n8k16 + helpers ----------------
__device__ __forceinline__ void mma_bf16(float c[4], const uint32_t a[4],
                                         uint32_t b0, uint32_t b1)
{
    asm volatile(
        "mma.sync.aligned.m16n8k16.row.col.f32.bf16.bf16.f32 "
        "{%0,%1,%2,%3}, {%4,%5,%6,%7}, {%8,%9}, {%0,%1,%2,%3};\n"
        : "+f"(c[0]), "+f"(c[1]), "+f"(c[2]), "+f"(c[3])
        : "r"(a[0]), "r"(a[1]), "r"(a[2]), "r"(a[3]), "r"(b0), "r"(b1));
}

__device__ __forceinline__ void split_pack(float x, float y, uint32_t& hi, uint32_t& lo)
{
    __nv_bfloat162 h = __floats2bfloat162_rn(x, y);
    float xr = x - __bfloat162float(h.x);
    float yr = y - __bfloat162float(h.y);
    __nv_bfloat162 l = __floats2bfloat162_rn(xr, yr);
    hi = *reinterpret_cast<uint32_t*>(&h);
    lo = *reinterpret_cast<uint32_t*>(&l);
}

// hi-only pack (P in PV: 2-term)
__device__ __forceinline__ uint32_t pack_hi(float x, float y)
{
    __nv_bfloat162 h = __floats2bfloat162_rn(x, y);
    return *reinterpret_cast<uint32_t*>(&h);
}

__device__ __forceinline__ float ex2(float x)
{
    float y;
    asm("ex2.approx.ftz.f32 %0, %1;" : "=f"(y) : "f"(x));
    return y;
}

// ---------------- kernel 1: depthwise conv 3x3 + BN ----------------
__global__ void prep_kernel(const float* __restrict__ x,
    const float* __restrict__ kq, const float* __restrict__ kk,
    const float* __restrict__ kv,
    const float* __restrict__ gq, const float* __restrict__ bq,
    const float* __restrict__ mq, const float* __restrict__ vq,
    const float* __restrict__ gk, const float* __restrict__ bk,
    const float* __restrict__ mk, const float* __restrict__ vk,
    const float* __restrict__ gv, const float* __restrict__ bv,
    const float* __restrict__ mv, const float* __restrict__ vv)
{
    int idx = blockIdx.x*blockDim.x + threadIdx.x;
    if (idx >= M_*C_) return;
    int c = idx % C_;
    int t = (idx / C_) % T_;
    int b = idx / (C_*T_);
    const float* xb = x + (size_t)b*T_*C_;
    if (t == 0) {
        float v = xb[c];
        g_qin[idx] = v; g_kin[idx] = v; g_vin[idx] = v;
        return;
    }
    int p = t - 1, py = p / HW, px = p % HW;
    float aq = 0.f, ak = 0.f, av = 0.f;
    #pragma unroll
    for (int dy = 0; dy < 3; dy++) {
        int ny = py + dy - 1;
        if ((unsigned)ny >= (unsigned)HW) continue;
        #pragma unroll
        for (int dx = 0; dx < 3; dx++) {
            int nx = px + dx - 1;
            if ((unsigned)nx >= (unsigned)HW) continue;
            float xv = xb[(size_t)(1 + ny*HW + nx)*C_ + c];
            int tap = dy*3 + dx;
            aq = fmaf(xv, kq[c*9 + tap], aq);
            ak = fmaf(xv, kk[c*9 + tap], ak);
            av = fmaf(xv, kv[c*9 + tap], av);
        }
    }
    g_qin[idx] = (aq - mq[c]) * (gq[c]*rsqrtf(vq[c]+BN_EPS)) + bq[c];
    g_kin[idx] = (ak - mk[c]) * (gk[c]*rsqrtf(vk[c]+BN_EPS)) + bk[c];
    g_vin[idx] = (av - mv[c]) * (gv[c]*rsqrtf(vv[c]+BN_EPS)) + bv[c];
}

// ============ GEMM building blocks (round-10, proven) ============
#define GEMM_SMEM_DECL \
    __shared__ __align__(16) uint32_t sA[128*32]; \
    __shared__ __align__(16) uint32_t sW[64*32]; \
    uint4* sA4 = reinterpret_cast<uint4*>(sA); \
    uint4* sW4 = reinterpret_cast<uint4*>(sW);

#define GEMM_STORE_A \
    _Pragma("unroll") \
    for (int tg = 0; tg < 4; tg++) { \
        float x0, x1, y0, y1; \
        if (tg & 1) { x0 = ra[tg>>1].z; x1 = ra[tg>>1].w; \
                      y0 = ra[2+(tg>>1)].z; y1 = ra[2+(tg>>1)].w; } \
        else        { x0 = ra[tg>>1].x; x1 = ra[tg>>1].y; \
                      y0 = ra[2+(tg>>1)].x; y1 = ra[2+(tg>>1)].y; } \
        uint32_t hA, lA, hB, lB; \
        split_pack(x0, x1, hA, lA); \
        split_pack(y0, y1, hB, lB); \
        sA4[arow*8 + SW(aks*4 + tg, arow)] = make_uint4(hA, hB, lA, lB); \
    }

#define GEMM_STORE_W \
    _Pragma("unroll") \
    for (int j = 0; j < 2; j++) { \
        float x0 = j ? rw0.z : rw0.x, x1 = j ? rw0.w : rw0.y; \
        float y0 = j ? rw1.z : rw1.x, y1 = j ? rw1.w : rw1.y; \
        uint32_t hA, lA, hB, lB; \
        split_pack(x0, x1, hA, lA); \
        split_pack(y0, y1, hB, lB); \
        int tg = 2*wq + j; \
        sW4[wrow*8 + SW(wks*4 + tg, wrow)] = make_uint4(hA, hB, lA, lB); \
    }

#define GEMM_MMA_BLOCK \
    _Pragma("unroll") \
    for (int ks = 0; ks < 2; ks++) { \
        int fs = ks*4 + tig; \
        uint4 a0 = sA4[(w*16+gid  )*8 + SW(fs, gid)]; \
        uint4 a1 = sA4[(w*16+gid+8)*8 + SW(fs, gid)]; \
        uint32_t ah[4] = {a0.x, a1.x, a0.y, a1.y}; \
        uint32_t al[4] = {a0.z, a1.z, a0.w, a1.w}; \
        _Pragma("unroll") \
        for (int ng = 0; ng < 2; ng++) { \
            uint4 u[4]; \
            _Pragma("unroll") \
            for (int j = 0; j < 4; j++) \
                u[j] = sW4[((ng*4+j)*8+gid)*8 + SW(fs, gid)]; \
            _Pragma("unroll") \
            for (int j = 0; j < 4; j++) mma_bf16(acc[ng*4+j], ah, u[j].x, u[j].y); \
            _Pragma("unroll") \
            for (int j = 0; j < 4; j++) mma_bf16(acc[ng*4+j], ah, u[j].z, u[j].w); \
            _Pragma("unroll") \
            for (int j = 0; j < 4; j++) mma_bf16(acc[ng*4+j], al, u[j].x, u[j].y); \
        } \
    }

#define GEMM_LOAD_W(k0off) \
    rw0 = *(const float4*)(W + (size_t)(n0 + wrow)*C_ + (k0off) + wks*16 + wq*4); \
    rw1 = *(const float4*)(W + (size_t)(n0 + wrow)*C_ + (k0off) + wks*16 + wq*4 + 8);

// ---------------- fused QKV GEMM (round-10 exact) ----------------
__global__ void __launch_bounds__(256) gemm_qkv(
    const float* __restrict__ Aq, const float* __restrict__ Ak, const float* __restrict__ Av,
    const float* __restrict__ Wq, const float* __restrict__ Wk, const float* __restrict__ Wv,
    float* __restrict__ Dq, float* __restrict__ Dv, uint32_t* __restrict__ Kp)
{
    GEMM_SMEM_DECL
    int z = blockIdx.z;
    const float* A = (z==0) ? Aq : (z==1) ? Ak : Av;
    const float* W = (z==0) ? Wq : (z==1) ? Wk : Wv;
    int m0 = blockIdx.x*128, n0 = blockIdx.y*64;
    int tid = threadIdx.x, w = tid>>5, lane = tid&31;
    int gid = lane>>2, tig = lane&3;
    float acc[8][4] = {};
    int arow = tid>>1, aks = tid&1;
    int wrow = tid>>2, wks = (tid>>1)&1, wq = tid&1;
    int gm = m0 + arow;

    float4 ra[4], rw0, rw1;
    #pragma unroll
    for (int i = 0; i < 4; i++)
        ra[i] = (gm < M_) ? *(const float4*)(A + (size_t)gm*C_ + aks*16 + i*4)
                          : make_float4(0.f,0.f,0.f,0.f);
    GEMM_LOAD_W(0)

    for (int k0 = 0; k0 < C_; k0 += 32) {
        GEMM_STORE_A
        GEMM_STORE_W
        __syncthreads();
        if (k0 + 32 < C_) {
            #pragma unroll
            for (int i = 0; i < 4; i++)
                ra[i] = (gm < M_) ? *(const float4*)(A + (size_t)gm*C_ + k0+32 + aks*16 + i*4)
                                  : make_float4(0.f,0.f,0.f,0.f);
            GEMM_LOAD_W(k0+32)
        }
        GEMM_MMA_BLOCK
        __syncthreads();
    }

    #pragma unroll
    for (int nt = 0; nt < 8; nt++) {
        int gn = n0 + nt*8 + 2*tig;
        #pragma unroll
        for (int half = 0; half < 2; half++) {
            int gmo = m0 + w*16 + gid + half*8;
            if (gmo >= M_) continue;
            float v0 = acc[nt][half*2+0], v1 = acc[nt][half*2+1];
            int b = gmo / T_, t = gmo % T_;
            int h = gn >> 6, d = gn & 63;
            if (z == 1) {
                uint32_t hi, lo;
                split_pack(v0, v1, hi, lo);
                size_t base = ((size_t)(b*H_ + h)*KT + t)*64;
                int s0 = pslot(d >> 1);
                Kp[base + s0] = hi; Kp[base + s0 + 2] = lo;
            } else {
                float* D = (z==0) ? Dq : Dv;
                float* p = &D[(((size_t)b*H_ + h)*T_ + t)*DH + d];
                p[0] = v0; p[1] = v1;
            }
        }
    }
}

// ---------------- output GEMM (round-10 exact, bias) ----------------
__global__ void __launch_bounds__(256) gemm_o(
    const float* __restrict__ A, const float* __restrict__ W,
    const float* __restrict__ bias, float* __restrict__ D)
{
    GEMM_SMEM_DECL
    int m0 = blockIdx.x*128, n0 = blockIdx.y*64;
    int tid = threadIdx.x, w = tid>>5, lane = tid&31;
    int gid = lane>>2, tig = lane&3;
    float acc[8][4] = {};
    int arow = tid>>1, aks = tid&1;
    int wrow = tid>>2, wks = (tid>>1)&1, wq = tid&1;
    int gm = m0 + arow;

    float4 ra[4], rw0, rw1;
    #pragma unroll
    for (int i = 0; i < 4; i++)
        ra[i] = (gm < M_) ? *(const float4*)(A + (size_t)gm*C_ + aks*16 + i*4)
                          : make_float4(0.f,0.f,0.f,0.f);
    GEMM_LOAD_W(0)

    for (int k0 = 0; k0 < C_; k0 += 32) {
        GEMM_STORE_A
        GEMM_STORE_W
        __syncthreads();
        if (k0 + 32 < C_) {
            #pragma unroll
            for (int i = 0; i < 4; i++)
                ra[i] = (gm < M_) ? *(const float4*)(A + (size_t)gm*C_ + k0+32 + aks*16 + i*4)
                                  : make_float4(0.f,0.f,0.f,0.f);
            GEMM_LOAD_W(k0+32)
        }
        GEMM_MMA_BLOCK
        __syncthreads();
    }

    #pragma unroll
    for (int nt = 0; nt < 8; nt++) {
        int gn = n0 + nt*8 + 2*tig;
        #pragma unroll
        for (int half = 0; half < 2; half++) {
            int gmo = m0 + w*16 + gid + half*8;
            if (gmo >= M_) continue;
            float* p = &D[(size_t)gmo*C_ + gn];
            p[0] = acc[nt][half*2+0] + bias[gn];
            p[1] = acc[nt][half*2+1] + bias[gn+1];
        }
    }
}

// ---------------- V transpose + interleaved pack ----------------
__global__ void __launch_bounds__(256) vpack(const float* __restrict__ V,
                                             uint32_t* __restrict__ Vt)
{
    __shared__ float tile[64][36];
    int bh = blockIdx.z, db = blockIdx.y*32, tileidx = blockIdx.x;
    int t0 = tileidx*64;
    int tid = threadIdx.x;
    {
        int tr = tid >> 2;
        int dc = (tid & 3) * 8;
        int gt = t0 + tr;
        if (gt < T_) {
            const float* src = V + ((size_t)bh*T_ + gt)*DH + db + dc;
            *(float4*)&tile[tr][dc]   = *(const float4*)src;
            *(float4*)&tile[tr][dc+4] = *(const float4*)(src + 4);
        } else {
            float4 z = make_float4(0.f,0.f,0.f,0.f);
            *(float4*)&tile[tr][dc]   = z;
            *(float4*)&tile[tr][dc+4] = z;
        }
    }
    __syncthreads();
    {
        int d = tid >> 3;
        int tpc = (tid & 7) * 4;
        size_t base = ((size_t)(bh*DH + db + d)*NKT + tileidx)*64;
        #pragma unroll
        for (int i = 0; i < 4; i++) {
            int p = tpc + i;
            uint32_t hi, lo;
            split_pack(tile[2*p][d], tile[2*p+1][d], hi, lo);
            int s0 = pslot(p);
            Vt[base + s0] = hi; Vt[base + s0 + 2] = lo;
        }
    }
}

// ---------------- flash attention: KV-split x3; 2-term QK, 2-term PV ----------------
#define QB 128
#define ASTR 80
#define KREG (64*ASTR)
#define BUFU (2*KREG)
#define ATTN_SMEM (2*BUFU*4)
__global__ void __launch_bounds__(256,2) attn_tc2(
    const float* __restrict__ Qh,
    const uint32_t* __restrict__ Kp, const uint32_t* __restrict__ Vt,
    float* __restrict__ po, float* __restrict__ pml)
{
    extern __shared__ uint32_t su[];
    const float SCALE = 0.05103103630798288f * 1.4426950408889634f;
    int bh = blockIdx.y, zt = blockIdx.z;
    int ts = (zt == 0) ? 0 : (zt == 1) ? 12 : 24;
    int te = (zt == 2) ? NKT : ts + 12;
    int q0 = blockIdx.x * QB;
    int tid = threadIdx.x, w = tid>>5, lane = tid&31;
    int gid = lane>>2, tig = lane&3;
    int r0 = q0 + w*16 + gid, r1 = r0 + 8;
    const float* Q = Qh + (size_t)bh*T_*DH;

    uint32_t qfh[4][4], qfl[4][4];
    #pragma unroll
    for (int ks = 0; ks < 4; ks++) {
        int c0 = ks*16 + 2*tig;
        float2 x0 = (r0 < T_) ? *(const float2*)(Q + (size_t)r0*DH + c0    ) : make_float2(0.f,0.f);
        float2 x1 = (r1 < T_) ? *(const float2*)(Q + (size_t)r1*DH + c0    ) : make_float2(0.f,0.f);
        float2 x2 = (r0 < T_) ? *(const float2*)(Q + (size_t)r0*DH + c0 + 8) : make_float2(0.f,0.f);
        float2 x3 = (r1 < T_) ? *(const float2*)(Q + (size_t)r1*DH + c0 + 8) : make_float2(0.f,0.f);
        split_pack(x0.x*SCALE, x0.y*SCALE, qfh[ks][0], qfl[ks][0]);
        split_pack(x1.x*SCALE, x1.y*SCALE, qfh[ks][1], qfl[ks][1]);
        split_pack(x2.x*SCALE, x2.y*SCALE, qfh[ks][2], qfl[ks][2]);
        split_pack(x3.x*SCALE, x3.y*SCALE, qfh[ks][3], qfl[ks][3]);
    }

    uint32_t sb = (uint32_t)__cvta_generic_to_shared(su);
    const uint32_t* gK = Kp + (size_t)bh*KT*64;
    const uint32_t* gV = Vt + (size_t)bh*DH*NKT*64;

    auto issue_tile = [&](int tile, int buf) {
        #pragma unroll
        for (int i = 0; i < 8; i++) {
            int idx = i*256 + tid;
            int arr = idx >> 10;
            int rem = idx & 1023;
            int row = rem >> 4, c4 = (rem & 15) * 4;
            const uint32_t* g = (arr == 0)
                ? gK + ((size_t)(tile*64 + row))*64 + c4
                : gV + ((size_t)row*NKT + tile)*64 + c4;
            uint32_t dst = sb + (buf*BUFU + arr*KREG + row*ASTR + c4)*4;
            asm volatile("cp.async.cg.shared.global [%0], [%1], 16;\n" :: "r"(dst), "l"(g));
        }
        asm volatile("cp.async.commit_group;\n");
    };

    float m0v = -1e30f, m1v = -1e30f, l0 = 0.f, l1 = 0.f;
    float o[8][4] = {};

    issue_tile(ts, 0);

    for (int it = ts; it < te; it++) {
        asm volatile("cp.async.wait_group 0;\n" ::: "memory");
        __syncthreads();
        if (it + 1 < te) issue_tile(it+1, (it+1-ts)&1);

        int buf = (it - ts) & 1;
        const uint4* bK4 = reinterpret_cast<const uint4*>(su + buf*BUFU);
        const uint4* bV4 = reinterpret_cast<const uint4*>(su + buf*BUFU + KREG);

        // S = Q @ K^T — 2-term: q_hi*k_hi + q_lo*k_hi (q_hi*k_lo dropped;
        // logit err ~1e-3 log2-units -> ~1e-4 final, budget 1e-3)
        float s[8][4] = {};
        #pragma unroll
        for (int ks = 0; ks < 4; ks++) {
            #pragma unroll
            for (int ng = 0; ng < 2; ng++) {
                uint4 u[4];
                #pragma unroll
                for (int j = 0; j < 4; j++)
                    u[j] = bK4[((ng*4+j)*8+gid)*(ASTR/4) + ks*4 + tig];
                #pragma unroll
                for (int j = 0; j < 4; j++) mma_bf16(s[ng*4+j], qfh[ks], u[j].x, u[j].y);
                #pragma unroll
                for (int j = 0; j < 4; j++) mma_bf16(s[ng*4+j], qfl[ks], u[j].x, u[j].y);
            }
        }

        if (it == NKT-1) {
            int j0 = it*64;
            #pragma unroll
            for (int nt = 0; nt < 8; nt++) {
                int cb = j0 + nt*8 + 2*tig;
                bool c0ok = cb < T_, c1ok = (cb+1) < T_;
                s[nt][0] = c0ok ? s[nt][0] : -1e30f;
                s[nt][1] = c1ok ? s[nt][1] : -1e30f;
                s[nt][2] = c0ok ? s[nt][2] : -1e30f;
                s[nt][3] = c1ok ? s[nt][3] : -1e30f;
            }
        }

        float mx0 = -1e30f, mx1 = -1e30f;
        #pragma unroll
        for (int nt = 0; nt < 8; nt++) {
            mx0 = fmaxf(mx0, fmaxf(s[nt][0], s[nt][1]));
            mx1 = fmaxf(mx1, fmaxf(s[nt][2], s[nt][3]));
        }
        mx0 = fmaxf(mx0, __shfl_xor_sync(0xffffffffu, mx0, 1));
        mx0 = fmaxf(mx0, __shfl_xor_sync(0xffffffffu, mx0, 2));
        mx1 = fmaxf(mx1, __shfl_xor_sync(0xffffffffu, mx1, 1));
        mx1 = fmaxf(mx1, __shfl_xor_sync(0xffffffffu, mx1, 2));

        float m0n = fmaxf(m0v, mx0), m1n = fmaxf(m1v, mx1);
        float a0 = ex2(m0v - m0n), a1 = ex2(m1v - m1n);
        float ps0 = 0.f, ps1 = 0.f;
        #pragma unroll
        for (int nt = 0; nt < 8; nt++) {
            s[nt][0] = ex2(s[nt][0] - m0n);
            s[nt][1] = ex2(s[nt][1] - m0n);
            s[nt][2] = ex2(s[nt][2] - m1n);
            s[nt][3] = ex2(s[nt][3] - m1n);
            ps0 += s[nt][0] + s[nt][1];
            ps1 += s[nt][2] + s[nt][3];
        }
        ps0 += __shfl_xor_sync(0xffffffffu, ps0, 1);
        ps0 += __shfl_xor_sync(0xffffffffu, ps0, 2);
        ps1 += __shfl_xor_sync(0xffffffffu, ps1, 1);
        ps1 += __shfl_xor_sync(0xffffffffu, ps1, 2);
        l0 = l0*a0 + ps0;  m0v = m0n;
        l1 = l1*a1 + ps1;  m1v = m1n;
        #pragma unroll
        for (int nt = 0; nt < 8; nt++) {
            o[nt][0] *= a0; o[nt][1] *= a0;
            o[nt][2] *= a1; o[nt][3] *= a1;
        }

        // O += P @ V  — P in bf16 hi only (2-term PV)
        #pragma unroll
        for (int ks = 0; ks < 4; ks++) {
            uint32_t ah[4];
            ah[0] = pack_hi(s[2*ks  ][0], s[2*ks  ][1]);
            ah[1] = pack_hi(s[2*ks  ][2], s[2*ks  ][3]);
            ah[2] = pack_hi(s[2*ks+1][0], s[2*ks+1][1]);
            ah[3] = pack_hi(s[2*ks+1][2], s[2*ks+1][3]);
            #pragma unroll
            for (int ng = 0; ng < 2; ng++) {
                uint4 u[4];
                #pragma unroll
                for (int j = 0; j < 4; j++)
                    u[j] = bV4[((ng*4+j)*8+gid)*(ASTR/4) + ks*4 + tig];
                #pragma unroll
                for (int j = 0; j < 4; j++) mma_bf16(o[ng*4+j], ah, u[j].x, u[j].y);
                #pragma unroll
                for (int j = 0; j < 4; j++) mma_bf16(o[ng*4+j], ah, u[j].z, u[j].w);
            }
        }
    }

    size_t pbase = (size_t)(bh*3 + zt) * QPAD;
    if (tig == 0) {
        if (r0 < T_) *(float2*)&pml[(pbase + r0)*2] = make_float2(m0v, l0);
        if (r1 < T_) *(float2*)&pml[(pbase + r1)*2] = make_float2(m1v, l1);
    }
    #pragma unroll
    for (int nt = 0; nt < 8; nt++) {
        int d = nt*8 + 2*tig;
        if (r0 < T_)
            *(float2*)&po[(pbase + r0)*64 + d] = make_float2(o[nt][0], o[nt][1]);
        if (r1 < T_)
            *(float2*)&po[(pbase + r1)*64 + d] = make_float2(o[nt][2], o[nt][3]);
    }
}

// ---------------- merge KV-split partials ----------------
__global__ void __launch_bounds__(256) merge_attn(
    const float* __restrict__ po, const float* __restrict__ pml,
    float* __restrict__ Oa)
{
    int idx = blockIdx.x*256 + threadIdx.x;
    if (idx >= BH_*T_*64) return;
    int d = idx & 63;
    int row = idx >> 6;
    int bh = row / T_, t = row - bh*T_;
    int b = bh / H_, h = bh - b*H_;
    size_t base = (size_t)bh*3*QPAD;
    float2 ml0 = *(const float2*)&pml[(base           + t)*2];
    float2 ml1 = *(const float2*)&pml[(base +   QPAD  + t)*2];
    float2 ml2 = *(const float2*)&pml[(base + 2*QPAD  + t)*2];
    float M = fmaxf(ml0.x, fmaxf(ml1.x, ml2.x));
    float w0 = ex2(ml0.x - M), w1 = ex2(ml1.x - M), w2 = ex2(ml2.x - M);
    float L = ml0.y*w0 + ml1.y*w1 + ml2.y*w2;
    float ov = po[(base          + t)*64 + d]*w0
             + po[(base +   QPAD + t)*64 + d]*w1
             + po[(base + 2*QPAD + t)*64 + d]*w2;
    Oa[((size_t)b*T_ + t)*C_ + h*DH + d] = ov / L;
}

// ---------------- launch ----------------
extern "C" void kernel_launch(void* const* d_in, const int* in_sizes, int n_in,
                              void* d_out, int out_size)
{
    const float* x  = (const float*)d_in[0];
    const float* kq = (const float*)d_in[3];
    const float* kk = (const float*)d_in[4];
    const float* kv = (const float*)d_in[5];
    const float* gq = (const float*)d_in[6];
    const float* bq = (const float*)d_in[7];
    const float* mq = (const float*)d_in[8];
    const float* vq = (const float*)d_in[9];
    const float* gk = (const float*)d_in[10];
    const float* bk = (const float*)d_in[11];
    const float* mk = (const float*)d_in[12];
    const float* vk = (const float*)d_in[13];
    const float* gv = (const float*)d_in[14];
    const float* bv = (const float*)d_in[15];
    const float* mv = (const float*)d_in[16];
    const float* vv = (const float*)d_in[17];
    const float* Wq = (const float*)d_in[18];
    const float* Wk = (const float*)d_in[19];
    const float* Wv = (const float*)d_in[20];
    const float* Wo = (const float*)d_in[21];
    const float* bo = (const float*)d_in[22];
    float* out = (float*)d_out;

    float *qin, *kin, *vin, *qh, *vh, *att, *po, *pml;
    uint32_t *kp, *vt;
    cudaGetSymbolAddress((void**)&qin, g_qin);
    cudaGetSymbolAddress((void**)&kin, g_kin);
    cudaGetSymbolAddress((void**)&vin, g_vin);
    cudaGetSymbolAddress((void**)&qh,  g_q);
    cudaGetSymbolAddress((void**)&vh,  g_v);
    cudaGetSymbolAddress((void**)&att, g_att);
    cudaGetSymbolAddress((void**)&kp,  g_kp);
    cudaGetSymbolAddress((void**)&vt,  g_vt);
    cudaGetSymbolAddress((void**)&po,  g_po);
    cudaGetSymbolAddress((void**)&pml, g_pml);

    prep_kernel<<<(M_*C_ + 255)/256, 256>>>(x, kq, kk, kv,
                                            gq, bq, mq, vq,
                                            gk, bk, mk, vk,
                                            gv, bv, mv, vv);

    dim3 gq3((M_ + 127)/128, C_/64, 3);
    gemm_qkv<<<gq3, 256>>>(qin, kin, vin, Wq, Wk, Wv, qh, vh, kp);

    vpack<<<dim3(NKT, DH/32, BH_), 256>>>(vh, vt);

    cudaFuncSetAttribute(attn_tc2,
                         cudaFuncAttributeMaxDynamicSharedMemorySize, ATTN_SMEM);
    attn_tc2<<<dim3((T_ + QB - 1)/QB, BH_, 3), 256, ATTN_SMEM>>>(qh, kp, vt, po, pml);

    merge_attn<<<(BH_*T_*64 + 255)/256, 256>>>(po, pml, att);

    gemm_o<<<dim3((M_ + 127)/128, C_/64), 256>>>(att, Wo, bo, out);
}

// round 17
// speedup vs baseline: 1.1693x; 1.0383x over previous
#include <cuda_runtime.h>
#include <cuda_bf16.h>
#include <math.h>
#include <stdint.h>

#define B_  4
#define T_  2305
#define C_  384
#define H_  6
#define BH_ (B_*H_)          // 24
#define DH  64
#define HW  48
#define M_  (B_*T_)          // 9220 rows
#define BN_EPS 1e-5f
#define NKT 37               // key tiles of 64
#define KT  (NKT*64)         // 2368 padded keys
#define QPAD 2432            // 19*128 padded queries

// Attention interleaved fragment layout (global K/V), unchanged since R8.
__device__ __forceinline__ int pslot(int p)   // returns hi slot (pair lo = +2)
{
    int t8 = p & 7;
    return (((p >> 3) * 4 + (t8 & 3)) << 2) + (t8 >> 2);
}

// GEMM smem swizzle (uint4 slot 0..7 xor row bits) — proven R9/R10.
#define SW(s,row) ((s) ^ ((((row)&1)<<2) ^ ((row)&3)))

// ---------------- device scratch (256B-aligned) ----------------
__device__ __align__(256) float g_qin[M_*C_];
__device__ __align__(256) float g_kin[M_*C_];
__device__ __align__(256) float g_vin[M_*C_];
__device__ __align__(256) float g_q  [M_*C_];            // (b,h,t,d) fp32
__device__ __align__(256) float g_v  [M_*C_];            // (b,h,t,d) fp32
__device__ __align__(256) uint32_t g_kp[BH_*KT*64];      // attention K frags
__device__ __align__(256) uint32_t g_vt[BH_*DH*NKT*64];  // attention V^T frags
__device__ __align__(256) float g_att[M_*C_];            // (b,t,c)
__device__ __align__(256) float g_po [BH_*3*QPAD*64];    // attention partial O
__device__ __align__(256) float g_pml[BH_*3*QPAD*2];     // attention partial (m,l)

// ---------------- bf16 mma m16n8k16 + helpers ----------------
__device__ __forceinline__ void mma_bf16(float c[4], const uint32_t a[4],
                                         uint32_t b0, uint32_t b1)
{
    asm volatile(
        "mma.sync.aligned.m16n8k16.row.col.f32.bf16.bf16.f32 "
        "{%0,%1,%2,%3}, {%4,%5,%6,%7}, {%8,%9}, {%0,%1,%2,%3};\n"
        : "+f"(c[0]), "+f"(c[1]), "+f"(c[2]), "+f"(c[3])
        : "r"(a[0]), "r"(a[1]), "r"(a[2]), "r"(a[3]), "r"(b0), "r"(b1));
}

__device__ __forceinline__ void split_pack(float x, float y, uint32_t& hi, uint32_t& lo)
{
    __nv_bfloat162 h = __floats2bfloat162_rn(x, y);
    float xr = x - __bfloat162float(h.x);
    float yr = y - __bfloat162float(h.y);
    __nv_bfloat162 l = __floats2bfloat162_rn(xr, yr);
    hi = *reinterpret_cast<uint32_t*>(&h);
    lo = *reinterpret_cast<uint32_t*>(&l);
}

// hi-only pack (P in PV; Q in QK: both 1-term now)
__device__ __forceinline__ uint32_t pack_hi(float x, float y)
{
    __nv_bfloat162 h = __floats2bfloat162_rn(x, y);
    return *reinterpret_cast<uint32_t*>(&h);
}

__device__ __forceinline__ float ex2(float x)
{
    float y;
    asm("ex2.approx.ftz.f32 %0, %1;" : "=f"(y) : "f"(x));
    return y;
}

// ---------------- kernel 1: depthwise conv 3x3 + BN ----------------
__global__ void prep_kernel(const float* __restrict__ x,
    const float* __restrict__ kq, const float* __restrict__ kk,
    const float* __restrict__ kv,
    const float* __restrict__ gq, const float* __restrict__ bq,
    const float* __restrict__ mq, const float* __restrict__ vq,
    const float* __restrict__ gk, const float* __restrict__ bk,
    const float* __restrict__ mk, const float* __restrict__ vk,
    const float* __restrict__ gv, const float* __restrict__ bv,
    const float* __restrict__ mv, const float* __restrict__ vv)
{
    int idx = blockIdx.x*blockDim.x + threadIdx.x;
    if (idx >= M_*C_) return;
    int c = idx % C_;
    int t = (idx / C_) % T_;
    int b = idx / (C_*T_);
    const float* xb = x + (size_t)b*T_*C_;
    if (t == 0) {
        float v = xb[c];
        g_qin[idx] = v; g_kin[idx] = v; g_vin[idx] = v;
        return;
    }
    int p = t - 1, py = p / HW, px = p % HW;
    float aq = 0.f, ak = 0.f, av = 0.f;
    #pragma unroll
    for (int dy = 0; dy < 3; dy++) {
        int ny = py + dy - 1;
        if ((unsigned)ny >= (unsigned)HW) continue;
        #pragma unroll
        for (int dx = 0; dx < 3; dx++) {
            int nx = px + dx - 1;
            if ((unsigned)nx >= (unsigned)HW) continue;
            float xv = xb[(size_t)(1 + ny*HW + nx)*C_ + c];
            int tap = dy*3 + dx;
            aq = fmaf(xv, kq[c*9 + tap], aq);
            ak = fmaf(xv, kk[c*9 + tap], ak);
            av = fmaf(xv, kv[c*9 + tap], av);
        }
    }
    g_qin[idx] = (aq - mq[c]) * (gq[c]*rsqrtf(vq[c]+BN_EPS)) + bq[c];
    g_kin[idx] = (ak - mk[c]) * (gk[c]*rsqrtf(vk[c]+BN_EPS)) + bk[c];
    g_vin[idx] = (av - mv[c]) * (gv[c]*rsqrtf(vv[c]+BN_EPS)) + bv[c];
}

// ============ GEMM building blocks (round-10, proven) ============
#define GEMM_SMEM_DECL \
    __shared__ __align__(16) uint32_t sA[128*32]; \
    __shared__ __align__(16) uint32_t sW[64*32]; \
    uint4* sA4 = reinterpret_cast<uint4*>(sA); \
    uint4* sW4 = reinterpret_cast<uint4*>(sW);

#define GEMM_STORE_A \
    _Pragma("unroll") \
    for (int tg = 0; tg < 4; tg++) { \
        float x0, x1, y0, y1; \
        if (tg & 1) { x0 = ra[tg>>1].z; x1 = ra[tg>>1].w; \
                      y0 = ra[2+(tg>>1)].z; y1 = ra[2+(tg>>1)].w; } \
        else        { x0 = ra[tg>>1].x; x1 = ra[tg>>1].y; \
                      y0 = ra[2+(tg>>1)].x; y1 = ra[2+(tg>>1)].y; } \
        uint32_t hA, lA, hB, lB; \
        split_pack(x0, x1, hA, lA); \
        split_pack(y0, y1, hB, lB); \
        sA4[arow*8 + SW(aks*4 + tg, arow)] = make_uint4(hA, hB, lA, lB); \
    }

#define GEMM_STORE_W \
    _Pragma("unroll") \
    for (int j = 0; j < 2; j++) { \
        float x0 = j ? rw0.z : rw0.x, x1 = j ? rw0.w : rw0.y; \
        float y0 = j ? rw1.z : rw1.x, y1 = j ? rw1.w : rw1.y; \
        uint32_t hA, lA, hB, lB; \
        split_pack(x0, x1, hA, lA); \
        split_pack(y0, y1, hB, lB); \
        int tg = 2*wq + j; \
        sW4[wrow*8 + SW(wks*4 + tg, wrow)] = make_uint4(hA, hB, lA, lB); \
    }

#define GEMM_MMA_BLOCK \
    _Pragma("unroll") \
    for (int ks = 0; ks < 2; ks++) { \
        int fs = ks*4 + tig; \
        uint4 a0 = sA4[(w*16+gid  )*8 + SW(fs, gid)]; \
        uint4 a1 = sA4[(w*16+gid+8)*8 + SW(fs, gid)]; \
        uint32_t ah[4] = {a0.x, a1.x, a0.y, a1.y}; \
        uint32_t al[4] = {a0.z, a1.z, a0.w, a1.w}; \
        _Pragma("unroll") \
        for (int ng = 0; ng < 2; ng++) { \
            uint4 u[4]; \
            _Pragma("unroll") \
            for (int j = 0; j < 4; j++) \
                u[j] = sW4[((ng*4+j)*8+gid)*8 + SW(fs, gid)]; \
            _Pragma("unroll") \
            for (int j = 0; j < 4; j++) mma_bf16(acc[ng*4+j], ah, u[j].x, u[j].y); \
            _Pragma("unroll") \
            for (int j = 0; j < 4; j++) mma_bf16(acc[ng*4+j], ah, u[j].z, u[j].w); \
            _Pragma("unroll") \
            for (int j = 0; j < 4; j++) mma_bf16(acc[ng*4+j], al, u[j].x, u[j].y); \
        } \
    }

#define GEMM_LOAD_W(k0off) \
    rw0 = *(const float4*)(W + (size_t)(n0 + wrow)*C_ + (k0off) + wks*16 + wq*4); \
    rw1 = *(const float4*)(W + (size_t)(n0 + wrow)*C_ + (k0off) + wks*16 + wq*4 + 8);

// ---------------- fused QKV GEMM (round-10 exact) ----------------
__global__ void __launch_bounds__(256) gemm_qkv(
    const float* __restrict__ Aq, const float* __restrict__ Ak, const float* __restrict__ Av,
    const float* __restrict__ Wq, const float* __restrict__ Wk, const float* __restrict__ Wv,
    float* __restrict__ Dq, float* __restrict__ Dv, uint32_t* __restrict__ Kp)
{
    GEMM_SMEM_DECL
    int z = blockIdx.z;
    const float* A = (z==0) ? Aq : (z==1) ? Ak : Av;
    const float* W = (z==0) ? Wq : (z==1) ? Wk : Wv;
    int m0 = blockIdx.x*128, n0 = blockIdx.y*64;
    int tid = threadIdx.x, w = tid>>5, lane = tid&31;
    int gid = lane>>2, tig = lane&3;
    float acc[8][4] = {};
    int arow = tid>>1, aks = tid&1;
    int wrow = tid>>2, wks = (tid>>1)&1, wq = tid&1;
    int gm = m0 + arow;

    float4 ra[4], rw0, rw1;
    #pragma unroll
    for (int i = 0; i < 4; i++)
        ra[i] = (gm < M_) ? *(const float4*)(A + (size_t)gm*C_ + aks*16 + i*4)
                          : make_float4(0.f,0.f,0.f,0.f);
    GEMM_LOAD_W(0)

    for (int k0 = 0; k0 < C_; k0 += 32) {
        GEMM_STORE_A
        GEMM_STORE_W
        __syncthreads();
        if (k0 + 32 < C_) {
            #pragma unroll
            for (int i = 0; i < 4; i++)
                ra[i] = (gm < M_) ? *(const float4*)(A + (size_t)gm*C_ + k0+32 + aks*16 + i*4)
                                  : make_float4(0.f,0.f,0.f,0.f);
            GEMM_LOAD_W(k0+32)
        }
        GEMM_MMA_BLOCK
        __syncthreads();
    }

    #pragma unroll
    for (int nt = 0; nt < 8; nt++) {
        int gn = n0 + nt*8 + 2*tig;
        #pragma unroll
        for (int half = 0; half < 2; half++) {
            int gmo = m0 + w*16 + gid + half*8;
            if (gmo >= M_) continue;
            float v0 = acc[nt][half*2+0], v1 = acc[nt][half*2+1];
            int b = gmo / T_, t = gmo % T_;
            int h = gn >> 6, d = gn & 63;
            if (z == 1) {
                uint32_t hi, lo;
                split_pack(v0, v1, hi, lo);
                size_t base = ((size_t)(b*H_ + h)*KT + t)*64;
                int s0 = pslot(d >> 1);
                Kp[base + s0] = hi; Kp[base + s0 + 2] = lo;
            } else {
                float* D = (z==0) ? Dq : Dv;
                float* p = &D[(((size_t)b*H_ + h)*T_ + t)*DH + d];
                p[0] = v0; p[1] = v1;
            }
        }
    }
}

// ---------------- output GEMM (round-10 exact, bias) ----------------
__global__ void __launch_bounds__(256) gemm_o(
    const float* __restrict__ A, const float* __restrict__ W,
    const float* __restrict__ bias, float* __restrict__ D)
{
    GEMM_SMEM_DECL
    int m0 = blockIdx.x*128, n0 = blockIdx.y*64;
    int tid = threadIdx.x, w = tid>>5, lane = tid&31;
    int gid = lane>>2, tig = lane&3;
    float acc[8][4] = {};
    int arow = tid>>1, aks = tid&1;
    int wrow = tid>>2, wks = (tid>>1)&1, wq = tid&1;
    int gm = m0 + arow;

    float4 ra[4], rw0, rw1;
    #pragma unroll
    for (int i = 0; i < 4; i++)
        ra[i] = (gm < M_) ? *(const float4*)(A + (size_t)gm*C_ + aks*16 + i*4)
                          : make_float4(0.f,0.f,0.f,0.f);
    GEMM_LOAD_W(0)

    for (int k0 = 0; k0 < C_; k0 += 32) {
        GEMM_STORE_A
        GEMM_STORE_W
        __syncthreads();
        if (k0 + 32 < C_) {
            #pragma unroll
            for (int i = 0; i < 4; i++)
                ra[i] = (gm < M_) ? *(const float4*)(A + (size_t)gm*C_ + k0+32 + aks*16 + i*4)
                                  : make_float4(0.f,0.f,0.f,0.f);
            GEMM_LOAD_W(k0+32)
        }
        GEMM_MMA_BLOCK
        __syncthreads();
    }

    #pragma unroll
    for (int nt = 0; nt < 8; nt++) {
        int gn = n0 + nt*8 + 2*tig;
        #pragma unroll
        for (int half = 0; half < 2; half++) {
            int gmo = m0 + w*16 + gid + half*8;
            if (gmo >= M_) continue;
            float* p = &D[(size_t)gmo*C_ + gn];
            p[0] = acc[nt][half*2+0] + bias[gn];
            p[1] = acc[nt][half*2+1] + bias[gn+1];
        }
    }
}

// ---------------- V transpose + interleaved pack ----------------
__global__ void __launch_bounds__(256) vpack(const float* __restrict__ V,
                                             uint32_t* __restrict__ Vt)
{
    __shared__ float tile[64][36];
    int bh = blockIdx.z, db = blockIdx.y*32, tileidx = blockIdx.x;
    int t0 = tileidx*64;
    int tid = threadIdx.x;
    {
        int tr = tid >> 2;
        int dc = (tid & 3) * 8;
        int gt = t0 + tr;
        if (gt < T_) {
            const float* src = V + ((size_t)bh*T_ + gt)*DH + db + dc;
            *(float4*)&tile[tr][dc]   = *(const float4*)src;
            *(float4*)&tile[tr][dc+4] = *(const float4*)(src + 4);
        } else {
            float4 z = make_float4(0.f,0.f,0.f,0.f);
            *(float4*)&tile[tr][dc]   = z;
            *(float4*)&tile[tr][dc+4] = z;
        }
    }
    __syncthreads();
    {
        int d = tid >> 3;
        int tpc = (tid & 7) * 4;
        size_t base = ((size_t)(bh*DH + db + d)*NKT + tileidx)*64;
        #pragma unroll
        for (int i = 0; i < 4; i++) {
            int p = tpc + i;
            uint32_t hi, lo;
            split_pack(tile[2*p][d], tile[2*p+1][d], hi, lo);
            int s0 = pslot(p);
            Vt[base + s0] = hi; Vt[base + s0 + 2] = lo;
        }
    }
}

// ---------------- flash attention: KV-split x3; pure-bf16 QK, 2-term PV ----------------
#define QB 128
#define ASTR 80
#define KREG (64*ASTR)
#define BUFU (2*KREG)
#define ATTN_SMEM (2*BUFU*4)
__global__ void __launch_bounds__(256,2) attn_tc2(
    const float* __restrict__ Qh,
    const uint32_t* __restrict__ Kp, const uint32_t* __restrict__ Vt,
    float* __restrict__ po, float* __restrict__ pml)
{
    extern __shared__ uint32_t su[];
    const float SCALE = 0.05103103630798288f * 1.4426950408889634f;
    int bh = blockIdx.y, zt = blockIdx.z;
    int ts = (zt == 0) ? 0 : (zt == 1) ? 12 : 24;
    int te = (zt == 2) ? NKT : ts + 12;
    int q0 = blockIdx.x * QB;
    int tid = threadIdx.x, w = tid>>5, lane = tid&31;
    int gid = lane>>2, tig = lane&3;
    int r0 = q0 + w*16 + gid, r1 = r0 + 8;
    const float* Q = Qh + (size_t)bh*T_*DH;

    // Q fragments, bf16 hi only (R16 measured the q*k_lo term at ~zero
    // accuracy impact; q_lo*k_hi is symmetric -> pure-bf16 QK)
    uint32_t qfh[4][4];
    #pragma unroll
    for (int ks = 0; ks < 4; ks++) {
        int c0 = ks*16 + 2*tig;
        float2 x0 = (r0 < T_) ? *(const float2*)(Q + (size_t)r0*DH + c0    ) : make_float2(0.f,0.f);
        float2 x1 = (r1 < T_) ? *(const float2*)(Q + (size_t)r1*DH + c0    ) : make_float2(0.f,0.f);
        float2 x2 = (r0 < T_) ? *(const float2*)(Q + (size_t)r0*DH + c0 + 8) : make_float2(0.f,0.f);
        float2 x3 = (r1 < T_) ? *(const float2*)(Q + (size_t)r1*DH + c0 + 8) : make_float2(0.f,0.f);
        qfh[ks][0] = pack_hi(x0.x*SCALE, x0.y*SCALE);
        qfh[ks][1] = pack_hi(x1.x*SCALE, x1.y*SCALE);
        qfh[ks][2] = pack_hi(x2.x*SCALE, x2.y*SCALE);
        qfh[ks][3] = pack_hi(x3.x*SCALE, x3.y*SCALE);
    }

    uint32_t sb = (uint32_t)__cvta_generic_to_shared(su);
    const uint32_t* gK = Kp + (size_t)bh*KT*64;
    const uint32_t* gV = Vt + (size_t)bh*DH*NKT*64;

    auto issue_tile = [&](int tile, int buf) {
        #pragma unroll
        for (int i = 0; i < 8; i++) {
            int idx = i*256 + tid;
            int arr = idx >> 10;
            int rem = idx & 1023;
            int row = rem >> 4, c4 = (rem & 15) * 4;
            const uint32_t* g = (arr == 0)
                ? gK + ((size_t)(tile*64 + row))*64 + c4
                : gV + ((size_t)row*NKT + tile)*64 + c4;
            uint32_t dst = sb + (buf*BUFU + arr*KREG + row*ASTR + c4)*4;
            asm volatile("cp.async.cg.shared.global [%0], [%1], 16;\n" :: "r"(dst), "l"(g));
        }
        asm volatile("cp.async.commit_group;\n");
    };

    float m0v = -1e30f, m1v = -1e30f, l0 = 0.f, l1 = 0.f;
    float o[8][4] = {};

    issue_tile(ts, 0);

    for (int it = ts; it < te; it++) {
        asm volatile("cp.async.wait_group 0;\n" ::: "memory");
        __syncthreads();
        if (it + 1 < te) issue_tile(it+1, (it+1-ts)&1);

        int buf = (it - ts) & 1;
        const uint4* bK4 = reinterpret_cast<const uint4*>(su + buf*BUFU);
        const uint4* bV4 = reinterpret_cast<const uint4*>(su + buf*BUFU + KREG);

        // S = Q @ K^T — pure bf16 (q_hi * k_hi)
        float s[8][4] = {};
        #pragma unroll
        for (int ks = 0; ks < 4; ks++) {
            #pragma unroll
            for (int ng = 0; ng < 2; ng++) {
                uint4 u[4];
                #pragma unroll
                for (int j = 0; j < 4; j++)
                    u[j] = bK4[((ng*4+j)*8+gid)*(ASTR/4) + ks*4 + tig];
                #pragma unroll
                for (int j = 0; j < 4; j++) mma_bf16(s[ng*4+j], qfh[ks], u[j].x, u[j].y);
            }
        }

        if (it == NKT-1) {
            int j0 = it*64;
            #pragma unroll
            for (int nt = 0; nt < 8; nt++) {
                int cb = j0 + nt*8 + 2*tig;
                bool c0ok = cb < T_, c1ok = (cb+1) < T_;
                s[nt][0] = c0ok ? s[nt][0] : -1e30f;
                s[nt][1] = c1ok ? s[nt][1] : -1e30f;
                s[nt][2] = c0ok ? s[nt][2] : -1e30f;
                s[nt][3] = c1ok ? s[nt][3] : -1e30f;
            }
        }

        float mx0 = -1e30f, mx1 = -1e30f;
        #pragma unroll
        for (int nt = 0; nt < 8; nt++) {
            mx0 = fmaxf(mx0, fmaxf(s[nt][0], s[nt][1]));
            mx1 = fmaxf(mx1, fmaxf(s[nt][2], s[nt][3]));
        }
        mx0 = fmaxf(mx0, __shfl_xor_sync(0xffffffffu, mx0, 1));
        mx0 = fmaxf(mx0, __shfl_xor_sync(0xffffffffu, mx0, 2));
        mx1 = fmaxf(mx1, __shfl_xor_sync(0xffffffffu, mx1, 1));
        mx1 = fmaxf(mx1, __shfl_xor_sync(0xffffffffu, mx1, 2));

        float m0n = fmaxf(m0v, mx0), m1n = fmaxf(m1v, mx1);
        float a0 = ex2(m0v - m0n), a1 = ex2(m1v - m1n);
        float ps0 = 0.f, ps1 = 0.f;
        #pragma unroll
        for (int nt = 0; nt < 8; nt++) {
            s[nt][0] = ex2(s[nt][0] - m0n);
            s[nt][1] = ex2(s[nt][1] - m0n);
            s[nt][2] = ex2(s[nt][2] - m1n);
            s[nt][3] = ex2(s[nt][3] - m1n);
            ps0 += s[nt][0] + s[nt][1];
            ps1 += s[nt][2] + s[nt][3];
        }
        ps0 += __shfl_xor_sync(0xffffffffu, ps0, 1);
        ps0 += __shfl_xor_sync(0xffffffffu, ps0, 2);
        ps1 += __shfl_xor_sync(0xffffffffu, ps1, 1);
        ps1 += __shfl_xor_sync(0xffffffffu, ps1, 2);
        l0 = l0*a0 + ps0;  m0v = m0n;
        l1 = l1*a1 + ps1;  m1v = m1n;
        #pragma unroll
        for (int nt = 0; nt < 8; nt++) {
            o[nt][0] *= a0; o[nt][1] *= a0;
            o[nt][2] *= a1; o[nt][3] *= a1;
        }

        // O += P @ V  — P in bf16 hi only; V 2-term (v_lo error doesn't average — keep)
        #pragma unroll
        for (int ks = 0; ks < 4; ks++) {
            uint32_t ah[4];
            ah[0] = pack_hi(s[2*ks  ][0], s[2*ks  ][1]);
            ah[1] = pack_hi(s[2*ks  ][2], s[2*ks  ][3]);
            ah[2] = pack_hi(s[2*ks+1][0], s[2*ks+1][1]);
            ah[3] = pack_hi(s[2*ks+1][2], s[2*ks+1][3]);
            #pragma unroll
            for (int ng = 0; ng < 2; ng++) {
                uint4 u[4];
                #pragma unroll
                for (int j = 0; j < 4; j++)
                    u[j] = bV4[((ng*4+j)*8+gid)*(ASTR/4) + ks*4 + tig];
                #pragma unroll
                for (int j = 0; j < 4; j++) mma_bf16(o[ng*4+j], ah, u[j].x, u[j].y);
                #pragma unroll
                for (int j = 0; j < 4; j++) mma_bf16(o[ng*4+j], ah, u[j].z, u[j].w);
            }
        }
    }

    size_t pbase = (size_t)(bh*3 + zt) * QPAD;
    if (tig == 0) {
        if (r0 < T_) *(float2*)&pml[(pbase + r0)*2] = make_float2(m0v, l0);
        if (r1 < T_) *(float2*)&pml[(pbase + r1)*2] = make_float2(m1v, l1);
    }
    #pragma unroll
    for (int nt = 0; nt < 8; nt++) {
        int d = nt*8 + 2*tig;
        if (r0 < T_)
            *(float2*)&po[(pbase + r0)*64 + d] = make_float2(o[nt][0], o[nt][1]);
        if (r1 < T_)
            *(float2*)&po[(pbase + r1)*64 + d] = make_float2(o[nt][2], o[nt][3]);
    }
}

// ---------------- merge KV-split partials ----------------
__global__ void __launch_bounds__(256) merge_attn(
    const float* __restrict__ po, const float* __restrict__ pml,
    float* __restrict__ Oa)
{
    int idx = blockIdx.x*256 + threadIdx.x;
    if (idx >= BH_*T_*64) return;
    int d = idx & 63;
    int row = idx >> 6;
    int bh = row / T_, t = row - bh*T_;
    int b = bh / H_, h = bh - b*H_;
    size_t base = (size_t)bh*3*QPAD;
    float2 ml0 = *(const float2*)&pml[(base           + t)*2];
    float2 ml1 = *(const float2*)&pml[(base +   QPAD  + t)*2];
    float2 ml2 = *(const float2*)&pml[(base + 2*QPAD  + t)*2];
    float M = fmaxf(ml0.x, fmaxf(ml1.x, ml2.x));
    float w0 = ex2(ml0.x - M), w1 = ex2(ml1.x - M), w2 = ex2(ml2.x - M);
    float L = ml0.y*w0 + ml1.y*w1 + ml2.y*w2;
    float ov = po[(base          + t)*64 + d]*w0
             + po[(base +   QPAD + t)*64 + d]*w1
             + po[(base + 2*QPAD + t)*64 + d]*w2;
    Oa[((size_t)b*T_ + t)*C_ + h*DH + d] = ov / L;
}

// ---------------- launch ----------------
extern "C" void kernel_launch(void* const* d_in, const int* in_sizes, int n_in,
                              void* d_out, int out_size)
{
    const float* x  = (const float*)d_in[0];
    const float* kq = (const float*)d_in[3];
    const float* kk = (const float*)d_in[4];
    const float* kv = (const float*)d_in[5];
    const float* gq = (const float*)d_in[6];
    const float* bq = (const float*)d_in[7];
    const float* mq = (const float*)d_in[8];
    const float* vq = (const float*)d_in[9];
    const float* gk = (const float*)d_in[10];
    const float* bk = (const float*)d_in[11];
    const float* mk = (const float*)d_in[12];
    const float* vk = (const float*)d_in[13];
    const float* gv = (const float*)d_in[14];
    const float* bv = (const float*)d_in[15];
    const float* mv = (const float*)d_in[16];
    const float* vv = (const float*)d_in[17];
    const float* Wq = (const float*)d_in[18];
    const float* Wk = (const float*)d_in[19];
    const float* Wv = (const float*)d_in[20];
    const float* Wo = (const float*)d_in[21];
    const float* bo = (const float*)d_in[22];
    float* out = (float*)d_out;

    float *qin, *kin, *vin, *qh, *vh, *att, *po, *pml;
    uint32_t *kp, *vt;
    cudaGetSymbolAddress((void**)&qin, g_qin);
    cudaGetSymbolAddress((void**)&kin, g_kin);
    cudaGetSymbolAddress((void**)&vin, g_vin);
    cudaGetSymbolAddress((void**)&qh,  g_q);
    cudaGetSymbolAddress((void**)&vh,  g_v);
    cudaGetSymbolAddress((void**)&att, g_att);
    cudaGetSymbolAddress((void**)&kp,  g_kp);
    cudaGetSymbolAddress((void**)&vt,  g_vt);
    cudaGetSymbolAddress((void**)&po,  g_po);
    cudaGetSymbolAddress((void**)&pml, g_pml);

    prep_kernel<<<(M_*C_ + 255)/256, 256>>>(x, kq, kk, kv,
                                            gq, bq, mq, vq,
                                            gk, bk, mk, vk,
                                            gv, bv, mv, vv);

    dim3 gq3((M_ + 127)/128, C_/64, 3);
    gemm_qkv<<<gq3, 256>>>(qin, kin, vin, Wq, Wk, Wv, qh, vh, kp);

    vpack<<<dim3(NKT, DH/32, BH_), 256>>>(vh, vt);

    cudaFuncSetAttribute(attn_tc2,
                         cudaFuncAttributeMaxDynamicSharedMemorySize, ATTN_SMEM);
    attn_tc2<<<dim3((T_ + QB - 1)/QB, BH_, 3), 256, ATTN_SMEM>>>(qh, kp, vt, po, pml);

    merge_attn<<<(BH_*T_*64 + 255)/256, 256>>>(po, pml, att);

    gemm_o<<<dim3((M_ + 127)/128, C_/64), 256>>>(att, Wo, bo, out);
}